// round 9
// baseline (speedup 1.0000x reference)
#include <cuda_runtime.h>
#include <math.h>

#define NB 128
#define NT 512

typedef unsigned long long u64;

// ---------------- device scratch ----------------
__device__ float g_h[1024 * 256];            // carry h  (1 MB)
__device__ float g_p[1024 * 8 * 256];        // p[b*512 + i*8 + r][d] (8 MB)
__device__ float g_ssp[3][1024 * 256];       // shift / scale / proj_x
__device__ int   g_len[16];
__device__ unsigned g_cnt;                   // grid barrier counter

// ---------------- f32x2 helpers ----------------
__device__ __forceinline__ void fma2(u64& d, u64 a, u64 b) {
    asm("fma.rn.f32x2 %0, %1, %2, %0;" : "+l"(d) : "l"(a), "l"(b));
}
__device__ __forceinline__ float psum(u64 v) {
    float a, b;
    asm("mov.b64 {%0,%1}, %2;" : "=f"(a), "=f"(b) : "l"(v));
    return a + b;
}

// ---------------- grid-wide barrier (all 128 CTAs resident: 1 CTA/SM) -------
__device__ __forceinline__ void gsync() {
    __syncthreads();
    if (threadIdx.x == 0) {
        __threadfence();                                   // release all prior writes
        unsigned ticket = atomicAdd(&g_cnt, 1u);
        unsigned target = (ticket | (NB - 1)) + 1;         // next multiple of NB
        unsigned v;
        do {
            asm volatile("ld.acquire.gpu.u32 %0, [%1];" : "=r"(v) : "l"(&g_cnt) : "memory");
        } while (v < target);
    }
    __syncthreads();
}

__global__ void k_reset() { g_cnt = 0u; }

// smem carve-out (floats):
//  GEMM phases: sX[1024] @0, sWt[256*34=8704] @1024, sRed @9728 (<=256)
//  phase B:     sAa[256] @0, sPt[8704] @1024, sH[2048] @9728, sRed[128] @11776
#define SM_TOTAL 11904

__global__ __launch_bounds__(NT, 1) void k_persist(
    const int*   __restrict__ tokens, const float* __restrict__ A,
    const float* __restrict__ root,   const float* __restrict__ emb,
    const float* __restrict__ Wp,     const float* __restrict__ bp,
    const float* __restrict__ W_in,   const float* __restrict__ b_in,
    const float* __restrict__ Wout,   const float* __restrict__ bout,
    float* __restrict__ out)
{
    __shared__ __align__(16) float sm[SM_TOTAL];
    const int tid  = threadIdx.x, lane = tid & 31, w = tid >> 5;
    const int bid  = blockIdx.x;

    // =================== prologue ===================
    for (int i = bid * NT + tid; i < 1024 * 256; i += NB * NT) g_h[i] = 0.0f;
    if (bid == 0 && tid < 16) {
        int c = 0;
        for (int l = 0; l < 64; l++) c += (tokens[l * 16 + tid] != 0);
        g_len[tid] = c;
    }
    // in_proj: 96 tiles (y<3 slots x 32 m-tiles), one per CTA
    if (bid < 96) {
        const int y = bid >> 5, m0 = (bid & 31) * 32;
        const int wm = w >> 2, wn = w & 3;                 // 4x4 warp grid
        float* sX = sm; float* sWt = sm + 1024;
        u64 acc[8][2];
#pragma unroll
        for (int v = 0; v < 8; v++) { acc[v][0] = 0ull; acc[v][1] = 0ull; }
        for (int k0 = 0; k0 < 256; k0 += 32) {
            for (int i = tid; i < 1024; i += NT) {
                int m = i >> 5, k = i & 31, row = m0 + m;
                int tok = tokens[(row & 63) * 16 + (row >> 6)];
                sX[i] = emb[tok * 256 + k0 + k];
            }
            for (int i = tid; i < 8192; i += NT) {
                int k = i >> 8, n = i & 255;
                sWt[n * 34 + k] = W_in[(k0 + k) * 768 + y * 256 + n];
            }
            __syncthreads();
#pragma unroll
            for (int kk = 0; kk < 16; kk++) {
                u64 a[8], wv[2];
#pragma unroll
                for (int v = 0; v < 8; v++)
                    a[v] = *(const u64*)&sX[(8 * wm + v) * 32 + 2 * kk];
#pragma unroll
                for (int u = 0; u < 2; u++)
                    wv[u] = *(const u64*)&sWt[(64 * wn + lane + 32 * u) * 34 + 2 * kk];
#pragma unroll
                for (int v = 0; v < 8; v++)
#pragma unroll
                    for (int u = 0; u < 2; u++) fma2(acc[v][u], a[v], wv[u]);
            }
            __syncthreads();
        }
#pragma unroll
        for (int v = 0; v < 8; v++) {
            int row = m0 + 8 * wm + v;
#pragma unroll
            for (int u = 0; u < 2; u++) {
                int c = 64 * wn + lane + 32 * u;
                g_ssp[y][row * 256 + c] = psum(acc[v][u]) + b_in[y * 256 + c];
            }
        }
    }
    gsync();

    // =================== 64 recurrent steps ===================
    for (int s = 0; s < 64; s++) {
        // ---------- phase A: p = LN(h @ Wp + bp), 256 tiles, 2 per CTA ----------
        for (int t = bid; t < 256; t += NB) {
            const int m0 = (t >> 3) * 32;
            const int r  = t & 7;
            const int wm = w >> 2, wn = w & 3;
            float* sX = sm; float* sWt = sm + 1024; float* sRed = sm + 9728;
            u64 acc[8][2];
#pragma unroll
            for (int v = 0; v < 8; v++) { acc[v][0] = 0ull; acc[v][1] = 0ull; }
            for (int k0 = 0; k0 < 256; k0 += 32) {
                for (int i = tid; i < 1024; i += NT) {
                    int m = i >> 5, k = i & 31;
                    sX[i] = __ldcg(&g_h[(m0 + m) * 256 + k0 + k]);
                }
                for (int i = tid; i < 8192; i += NT) {
                    int k = i >> 8, n = i & 255;
                    sWt[n * 34 + k] = Wp[(k0 + k) * 2048 + r * 256 + n];
                }
                __syncthreads();
#pragma unroll
                for (int kk = 0; kk < 16; kk++) {
                    u64 a[8], wv[2];
#pragma unroll
                    for (int v = 0; v < 8; v++)
                        a[v] = *(const u64*)&sX[(8 * wm + v) * 32 + 2 * kk];
#pragma unroll
                    for (int u = 0; u < 2; u++)
                        wv[u] = *(const u64*)&sWt[(64 * wn + lane + 32 * u) * 34 + 2 * kk];
#pragma unroll
                    for (int v = 0; v < 8; v++)
#pragma unroll
                        for (int u = 0; u < 2; u++) fma2(acc[v][u], a[v], wv[u]);
                }
                __syncthreads();
            }
            // bias + per-row LayerNorm over 256 cols (4 wn warps cooperate)
            float x[8][2];
            float bpv[2];
#pragma unroll
            for (int u = 0; u < 2; u++) bpv[u] = bp[r * 256 + 64 * wn + lane + 32 * u];
#pragma unroll
            for (int v = 0; v < 8; v++) {
#pragma unroll
                for (int u = 0; u < 2; u++) x[v][u] = psum(acc[v][u]) + bpv[u];
                float sv  = x[v][0] + x[v][1];
                float sv2 = x[v][0] * x[v][0] + x[v][1] * x[v][1];
#pragma unroll
                for (int o = 16; o > 0; o >>= 1) {
                    sv  += __shfl_xor_sync(0xffffffffu, sv,  o);
                    sv2 += __shfl_xor_sync(0xffffffffu, sv2, o);
                }
                if (lane == 0) {
                    sRed[(8 * wm + v) * 8 + wn * 2 + 0] = sv;
                    sRed[(8 * wm + v) * 8 + wn * 2 + 1] = sv2;
                }
            }
            __syncthreads();
#pragma unroll
            for (int v = 0; v < 8; v++) {
                int row = 8 * wm + v;
                float sv = 0.0f, sv2 = 0.0f;
#pragma unroll
                for (int q = 0; q < 4; q++) {
                    sv  += sRed[row * 8 + q * 2 + 0];
                    sv2 += sRed[row * 8 + q * 2 + 1];
                }
                float mean = sv * (1.0f / 256.0f);
                float var  = sv2 * (1.0f / 256.0f) - mean * mean;
                float inv  = rsqrtf(var + 1e-5f);
#pragma unroll
                for (int u = 0; u < 2; u++) {
                    int c = 64 * wn + lane + 32 * u;
                    g_p[((m0 + row) * 8 + r) * 256 + c] = (x[v][u] - mean) * inv;
                }
            }
            __syncthreads();
        }
        gsync();

        // ---------- phase B: einsum + shrink + LN + gate + out GEMM + tanh + mask ----
        {
            const int b = bid >> 3, jc = bid & 7, j0 = jc * 8;
            const int wm = w >> 3, wn = w & 7;            // 2x8 warp grid
            const int c  = 32 * wn + lane;                // one col per thread
            float* sAa = sm; float* sPt = sm + 1024; float* sH = sm + 9728;
            float* sRed = sm + 11776;
            u64 acc[4];
#pragma unroll
            for (int v = 0; v < 4; v++) acc[v] = 0ull;
            for (int kt = 0; kt < 16; kt++) {
                if (tid < 256) {
                    int row = tid >> 5, kk = tid & 31;
                    int kg = kt * 32 + kk, i = kg >> 3, hh = kg & 7;
                    sAa[row * 32 + kk] = A[((b * 64 + i) * 64 + (j0 + row)) * 8 + hh];
                }
                for (int i = tid; i < 8192; i += NT) {
                    int kk = i >> 8, d = i & 255;
                    sPt[d * 34 + kk] = __ldcg(&g_p[(b * 512 + kt * 32 + kk) * 256 + d]);
                }
                __syncthreads();
#pragma unroll
                for (int kk = 0; kk < 16; kk++) {
                    u64 a[4];
#pragma unroll
                    for (int v = 0; v < 4; v++)
                        a[v] = *(const u64*)&sAa[(4 * wm + v) * 32 + 2 * kk];
                    u64 wv = *(const u64*)&sPt[c * 34 + 2 * kk];
#pragma unroll
                    for (int v = 0; v < 4; v++) fma2(acc[v], a[v], wv);
                }
                __syncthreads();
            }
            // shrink + proj_x, LN partials
            float tv[4];
#pragma unroll
            for (int v = 0; v < 4; v++) {
                int gr = b * 64 + j0 + 4 * wm + v;
                float lin = psum(acc[v]);
                tv[v] = g_ssp[2][gr * 256 + c] + lin - tanhf(lin);
                float sv = tv[v], sv2 = tv[v] * tv[v];
#pragma unroll
                for (int o = 16; o > 0; o >>= 1) {
                    sv  += __shfl_xor_sync(0xffffffffu, sv,  o);
                    sv2 += __shfl_xor_sync(0xffffffffu, sv2, o);
                }
                if (lane == 0) {
                    sRed[(4 * wm + v) * 16 + wn * 2 + 0] = sv;
                    sRed[(4 * wm + v) * 16 + wn * 2 + 1] = sv2;
                }
            }
            __syncthreads();
#pragma unroll
            for (int v = 0; v < 4; v++) {
                int row = 4 * wm + v, gr = b * 64 + j0 + row;
                float sv = 0.0f, sv2 = 0.0f;
#pragma unroll
                for (int q = 0; q < 8; q++) {
                    sv  += sRed[row * 16 + q * 2 + 0];
                    sv2 += sRed[row * 16 + q * 2 + 1];
                }
                float mean = sv * (1.0f / 256.0f);
                float var  = sv2 * (1.0f / 256.0f) - mean * mean;
                float inv  = rsqrtf(var + 1e-5f);
                float ln   = (tv[v] - mean) * inv;
                float hv   = g_ssp[0][gr * 256 + c] * ln + g_ssp[1][gr * 256 + c];
                sH[row * 256 + c] = fmaxf(hv, 0.0f);
            }
            __syncthreads();
            // out GEMM: y = tanh(h @ Wout + bout)
            u64 acc2[4];
#pragma unroll
            for (int v = 0; v < 4; v++) acc2[v] = 0ull;
            for (int kt = 0; kt < 8; kt++) {
                for (int i = tid; i < 8192; i += NT) {
                    int k = i >> 8, n = i & 255;
                    sPt[n * 34 + k] = Wout[(kt * 32 + k) * 256 + n];
                }
                __syncthreads();
#pragma unroll
                for (int kk = 0; kk < 16; kk++) {
                    u64 a[4];
#pragma unroll
                    for (int v = 0; v < 4; v++)
                        a[v] = *(const u64*)&sH[(4 * wm + v) * 256 + kt * 32 + 2 * kk];
                    u64 wv = *(const u64*)&sPt[c * 34 + 2 * kk];
#pragma unroll
                    for (int v = 0; v < 4; v++) fma2(acc2[v], a[v], wv);
                }
                __syncthreads();
            }
            bool mz = ((64 - s) > g_len[b]);
            float bo = bout[c];
#pragma unroll
            for (int v = 0; v < 4; v++) {
                int gr = b * 64 + j0 + 4 * wm + v;
                float yv = tanhf(psum(acc2[v]) + bo);
                g_h[gr * 256 + c] = mz ? 0.0f : yv;
            }
        }
        gsync();
    }

    // =================== final reduction ===================
    if (bid < 16 && tid < 256) {
        float sdot = 0.0f;
        for (int i = 0; i < 64; i++)
            sdot += __ldcg(&g_h[(bid * 64 + i) * 256 + tid]) * root[bid * 64 + i];
        out[bid * 256 + tid] = sdot;
    }
}

extern "C" void kernel_launch(void* const* d_in, const int* in_sizes, int n_in,
                              void* d_out, int out_size) {
    const int*   tokens = (const int*)  d_in[0];
    const float* A      = (const float*)d_in[1];
    const float* root   = (const float*)d_in[2];
    const float* emb    = (const float*)d_in[3];
    const float* Wp     = (const float*)d_in[4];
    const float* bp     = (const float*)d_in[5];
    const float* W_in   = (const float*)d_in[6];
    const float* b_in   = (const float*)d_in[7];
    const float* Wout   = (const float*)d_in[8];
    const float* bout   = (const float*)d_in[9];
    float* out = (float*)d_out;

    k_reset<<<1, 1>>>();
    k_persist<<<NB, NT>>>(tokens, A, root, emb, Wp, bp, W_in, b_in, Wout, bout, out);
}

// round 10
// speedup vs baseline: 1.7322x; 1.7322x over previous
#include <cuda_runtime.h>
#include <math.h>

#define NB 128
#define NT 512

typedef unsigned long long u64;

// ---------------- device scratch ----------------
__device__ float g_h[1024 * 256];            // carry h (1 MB)
__device__ float g_p[1024 * 8 * 256];        // p[(b*64+i)*8+r][d] (8 MB)
__device__ float g_ssp[3][1024 * 256];       // shift / scale / proj_x
__device__ int   g_len[16];
__device__ unsigned g_cnt;

// ---------------- f32x2 helpers ----------------
__device__ __forceinline__ void fma2(u64& d, u64 a, u64 b) {
    asm("fma.rn.f32x2 %0, %1, %2, %0;" : "+l"(d) : "l"(a), "l"(b));
}
__device__ __forceinline__ float psum(u64 v) {
    float a, b;
    asm("mov.b64 {%0,%1}, %2;" : "=f"(a), "=f"(b) : "l"(v));
    return a + b;
}
__device__ __forceinline__ u64 pk(float lo, float hi) {
    u64 r;
    asm("mov.b64 %0, {%1,%2};" : "=l"(r) : "f"(lo), "f"(hi));
    return r;
}

// ---------------- grid barrier (128 CTAs, all resident) ----------------
__device__ __forceinline__ void gsync() {
    __syncthreads();
    if (threadIdx.x == 0) {
        __threadfence();
        unsigned ticket = atomicAdd(&g_cnt, 1u);
        unsigned target = (ticket | (NB - 1)) + 1;
        unsigned v;
        do {
            asm volatile("ld.acquire.gpu.u32 %0, [%1];" : "=r"(v) : "l"(&g_cnt) : "memory");
        } while (v < target);
    }
    __syncthreads();
}

__global__ void k_reset() { g_cnt = 0u; }

// ---------------- GEMM micro-kernels ----------------
// A-style: warp = 8 rows x 128 cols, chunk = 32 k. sW [32][256] natural, sX [64][32].
__device__ __forceinline__ void gemm_8x4(u64 (&acc)[8][4], const float* __restrict__ sW,
                                         const float* __restrict__ sX, int wm, int wn, int lane) {
#pragma unroll 2
    for (int kk2 = 0; kk2 < 8; kk2++) {
        const int kb = 4 * kk2;
        u64 wp[4][2];
#pragma unroll
        for (int u = 0; u < 4; u++) {
            int n = 128 * wn + 32 * u + lane;
            wp[u][0] = pk(sW[(kb + 0) * 256 + n], sW[(kb + 1) * 256 + n]);
            wp[u][1] = pk(sW[(kb + 2) * 256 + n], sW[(kb + 3) * 256 + n]);
        }
#pragma unroll
        for (int v = 0; v < 8; v++) {
            float4 af = *(const float4*)&sX[(8 * wm + v) * 32 + kb];
            u64 a01 = pk(af.x, af.y), a23 = pk(af.z, af.w);
#pragma unroll
            for (int u = 0; u < 4; u++) {
                fma2(acc[v][u], a01, wp[u][0]);
                fma2(acc[v][u], a23, wp[u][1]);
            }
        }
    }
}

// B-style: warp = 8 rows x 64 cols x 8-k subslice of a 32-k chunk (4-way k-split over ws).
__device__ __forceinline__ void gemm_8x2(u64 (&acc)[8][2], const float* __restrict__ sW,
                                         const float* __restrict__ sA, int aRow, int aK,
                                         int wn, int lane, int ws) {
#pragma unroll
    for (int kk2 = 0; kk2 < 2; kk2++) {
        const int kb = ws * 8 + 4 * kk2;
        u64 wp[2][2];
#pragma unroll
        for (int u = 0; u < 2; u++) {
            int n = 64 * wn + 32 * u + lane;
            wp[u][0] = pk(sW[(kb + 0) * 256 + n], sW[(kb + 1) * 256 + n]);
            wp[u][1] = pk(sW[(kb + 2) * 256 + n], sW[(kb + 3) * 256 + n]);
        }
#pragma unroll
        for (int v = 0; v < 8; v++) {
            float4 af = *(const float4*)&sA[v * aRow + aK + kb];
            u64 a01 = pk(af.x, af.y), a23 = pk(af.z, af.w);
            fma2(acc[v][0], a01, wp[0][0]);
            fma2(acc[v][0], a23, wp[0][1]);
            fma2(acc[v][1], a01, wp[1][0]);
            fma2(acc[v][1], a23, wp[1][1]);
        }
    }
}

// smem float layout:
//  buf0 @0     (8192): sW / sP / sWo staging + k-split reduction scratch (time-shared)
//  A:   sX @8192 (2048), sRedA @10240 (256)
//  B:   sA @8192 (256),  sH @8448 (2048), sRedLN @10496 (64)
#define SM_FLOATS 10752

__global__ __launch_bounds__(NT, 1) void k_persist(
    const int*   __restrict__ tokens, const float* __restrict__ A,
    const float* __restrict__ root,   const float* __restrict__ emb,
    const float* __restrict__ Wp,     const float* __restrict__ bp,
    const float* __restrict__ W_in,   const float* __restrict__ b_in,
    const float* __restrict__ Wout,   const float* __restrict__ bout,
    float* __restrict__ out)
{
    __shared__ __align__(16) float sm[SM_FLOATS];
    const int tid = threadIdx.x, lane = tid & 31, w = tid >> 5;
    const int bid = blockIdx.x;

    // =================== prologue ===================
    {   // zero carry: exactly one float4 per thread (128*512*4 = 262144)
        int i = (bid * NT + tid) * 4;
        *(float4*)&g_h[i] = make_float4(0.f, 0.f, 0.f, 0.f);
    }
    if (bid == 0 && tid < 16) {
        int c = 0;
        for (int l = 0; l < 64; l++) c += (tokens[l * 16 + tid] != 0);
        g_len[tid] = c;
    }
    // in_proj: 48 tiles (3 slots x 16 m-tiles of 64 rows)
    if (bid < 48) {
        const int y = bid >> 4, m0 = (bid & 15) * 64;
        const int wm = w >> 1, wn = w & 1;
        float* sW = sm; float* sX = sm + 8192;
        u64 acc[8][4];
#pragma unroll
        for (int v = 0; v < 8; v++)
#pragma unroll
            for (int u = 0; u < 4; u++) acc[v][u] = 0ull;

        float4 wreg[4], xreg;
#pragma unroll
        for (int q = 0; q < 4; q++) {
            int idx = tid + q * NT, kk = idx >> 6, n4 = idx & 63;
            wreg[q] = __ldg((const float4*)&W_in[kk * 768 + y * 256 + 4 * n4]);
        }
        {
            int m = tid >> 3, k4 = tid & 7, row = m0 + m;
            int tok = __ldg(&tokens[(row & 63) * 16 + (row >> 6)]);
            xreg = __ldg((const float4*)&emb[tok * 256 + 4 * k4]);
        }
        for (int kc = 0; kc < 8; kc++) {
            __syncthreads();
#pragma unroll
            for (int q = 0; q < 4; q++) {
                int idx = tid + q * NT, kk = idx >> 6, n4 = idx & 63;
                *(float4*)&sW[kk * 256 + 4 * n4] = wreg[q];
            }
            { int m = tid >> 3, k4 = tid & 7; *(float4*)&sX[m * 32 + 4 * k4] = xreg; }
            __syncthreads();
            if (kc < 7) {
                int k0 = (kc + 1) * 32;
#pragma unroll
                for (int q = 0; q < 4; q++) {
                    int idx = tid + q * NT, kk = idx >> 6, n4 = idx & 63;
                    wreg[q] = __ldg((const float4*)&W_in[(k0 + kk) * 768 + y * 256 + 4 * n4]);
                }
                int m = tid >> 3, k4 = tid & 7, row = m0 + m;
                int tok = __ldg(&tokens[(row & 63) * 16 + (row >> 6)]);
                xreg = __ldg((const float4*)&emb[tok * 256 + k0 + 4 * k4]);
            }
            gemm_8x4(acc, sW, sX, wm, wn, lane);
        }
#pragma unroll
        for (int v = 0; v < 8; v++) {
            int row = m0 + 8 * wm + v;
#pragma unroll
            for (int u = 0; u < 4; u++) {
                int n = 128 * wn + 32 * u + lane;
                g_ssp[y][row * 256 + n] = psum(acc[v][u]) + __ldg(&b_in[y * 256 + n]);
            }
        }
    }
    gsync();

    // =================== 64 recurrent steps ===================
    for (int st = 0; st < 64; st++) {
        // ---------- phase A: p = LN(h @ Wp_r + bp_r); CTA = 64 rows x one r ----------
        {
            const int m0 = (bid >> 3) * 64;
            const int r  = bid & 7;
            const int wm = w >> 1, wn = w & 1;
            float* sW = sm; float* sX = sm + 8192; float* sRed = sm + 10240;
            u64 acc[8][4];
#pragma unroll
            for (int v = 0; v < 8; v++)
#pragma unroll
                for (int u = 0; u < 4; u++) acc[v][u] = 0ull;

            float4 wreg[4], xreg;
#pragma unroll
            for (int q = 0; q < 4; q++) {
                int idx = tid + q * NT, kk = idx >> 6, n4 = idx & 63;
                wreg[q] = __ldg((const float4*)&Wp[kk * 2048 + r * 256 + 4 * n4]);
            }
            {
                int m = tid >> 3, k4 = tid & 7;
                xreg = __ldcg((const float4*)&g_h[(m0 + m) * 256 + 4 * k4]);
            }
            for (int kc = 0; kc < 8; kc++) {
                __syncthreads();
#pragma unroll
                for (int q = 0; q < 4; q++) {
                    int idx = tid + q * NT, kk = idx >> 6, n4 = idx & 63;
                    *(float4*)&sW[kk * 256 + 4 * n4] = wreg[q];
                }
                { int m = tid >> 3, k4 = tid & 7; *(float4*)&sX[m * 32 + 4 * k4] = xreg; }
                __syncthreads();
                if (kc < 7) {
                    int k0 = (kc + 1) * 32;
#pragma unroll
                    for (int q = 0; q < 4; q++) {
                        int idx = tid + q * NT, kk = idx >> 6, n4 = idx & 63;
                        wreg[q] = __ldg((const float4*)&Wp[(k0 + kk) * 2048 + r * 256 + 4 * n4]);
                    }
                    int m = tid >> 3, k4 = tid & 7;
                    xreg = __ldcg((const float4*)&g_h[(m0 + m) * 256 + k0 + 4 * k4]);
                }
                gemm_8x4(acc, sW, sX, wm, wn, lane);
            }
            // bias + per-row LayerNorm (row spans 2 wn warps)
            float x[8][4];
#pragma unroll
            for (int v = 0; v < 8; v++) {
                float s = 0.f, s2 = 0.f;
#pragma unroll
                for (int u = 0; u < 4; u++) {
                    int n = 128 * wn + 32 * u + lane;
                    x[v][u] = psum(acc[v][u]) + __ldg(&bp[r * 256 + n]);
                    s  += x[v][u];
                    s2 += x[v][u] * x[v][u];
                }
#pragma unroll
                for (int o = 16; o > 0; o >>= 1) {
                    s  += __shfl_xor_sync(0xffffffffu, s,  o);
                    s2 += __shfl_xor_sync(0xffffffffu, s2, o);
                }
                if (lane == 0) {
                    sRed[(8 * wm + v) * 4 + 2 * wn + 0] = s;
                    sRed[(8 * wm + v) * 4 + 2 * wn + 1] = s2;
                }
            }
            __syncthreads();
#pragma unroll
            for (int v = 0; v < 8; v++) {
                int row = 8 * wm + v;
                float s  = sRed[row * 4 + 0] + sRed[row * 4 + 2];
                float s2 = sRed[row * 4 + 1] + sRed[row * 4 + 3];
                float mean = s * (1.0f / 256.0f);
                float var  = s2 * (1.0f / 256.0f) - mean * mean;
                float inv  = rsqrtf(var + 1e-5f);
#pragma unroll
                for (int u = 0; u < 4; u++) {
                    int n = 128 * wn + 32 * u + lane;
                    g_p[((m0 + row) * 8 + r) * 256 + n] = (x[v][u] - mean) * inv;
                }
            }
        }
        gsync();

        // ---------- phase B: einsum + shrink + LN + gate + outGEMM + tanh + mask ----------
        {
            const int b = bid >> 3, j0 = (bid & 7) * 8;
            const int wn = w & 3, ws = w >> 2;               // 4 col-groups x 4 k-slices
            float* buf0 = sm;                 // sP / sWo staging + reduction scratch
            float* sA   = sm + 8192;
            float* sH   = sm + 8448;
            float* sRedLN = sm + 10496;

            // ----- einsum over K=512 (16 chunks of 32) -----
            u64 acc[8][2];
#pragma unroll
            for (int v = 0; v < 8; v++) { acc[v][0] = 0ull; acc[v][1] = 0ull; }

            float4 preg[4]; float areg = 0.f;
#pragma unroll
            for (int q = 0; q < 4; q++) {
                int idx = tid + q * NT, kk = idx >> 6, n4 = idx & 63;
                preg[q] = __ldcg((const float4*)&g_p[(b * 512 + kk) * 256 + 4 * n4]);
            }
            if (tid < 256) {
                int jr = tid >> 5, kk = tid & 31;
                areg = __ldg(&A[((b * 64 + (kk >> 3)) * 64 + j0 + jr) * 8 + (kk & 7)]);
            }
            for (int kt = 0; kt < 16; kt++) {
                __syncthreads();
#pragma unroll
                for (int q = 0; q < 4; q++) {
                    int idx = tid + q * NT, kk = idx >> 6, n4 = idx & 63;
                    *(float4*)&buf0[kk * 256 + 4 * n4] = preg[q];
                }
                if (tid < 256) sA[tid] = areg;
                __syncthreads();
                if (kt < 15) {
                    int K0 = (kt + 1) * 32;
#pragma unroll
                    for (int q = 0; q < 4; q++) {
                        int idx = tid + q * NT, kk = idx >> 6, n4 = idx & 63;
                        preg[q] = __ldcg((const float4*)&g_p[(b * 512 + K0 + kk) * 256 + 4 * n4]);
                    }
                    if (tid < 256) {
                        int jr = tid >> 5, kk = K0 + (tid & 31);
                        areg = __ldg(&A[((b * 64 + (kk >> 3)) * 64 + j0 + jr) * 8 + (kk & 7)]);
                    }
                }
                gemm_8x2(acc, buf0, sA, 32, 0, wn, lane, ws);
            }
            __syncthreads();                                  // everyone done reading buf0
            // k-split reduction (ws 1..3 -> buf0), then shrink + LN + gate on ws==0
            float x[8][2];
#pragma unroll
            for (int v = 0; v < 8; v++) { x[v][0] = psum(acc[v][0]); x[v][1] = psum(acc[v][1]); }
            if (ws > 0) {
#pragma unroll
                for (int v = 0; v < 8; v++)
#pragma unroll
                    for (int u = 0; u < 2; u++) {
                        int n = 64 * wn + 32 * u + lane;
                        buf0[(ws - 1) * 2048 + v * 256 + n] = x[v][u];
                    }
            }
            __syncthreads();
            float t[8][2];
            if (ws == 0) {
#pragma unroll
                for (int v = 0; v < 8; v++) {
                    int gr = b * 64 + j0 + v;
                    float s = 0.f, s2 = 0.f;
#pragma unroll
                    for (int u = 0; u < 2; u++) {
                        int n = 64 * wn + 32 * u + lane;
                        float lin = x[v][u] + buf0[v * 256 + n] + buf0[2048 + v * 256 + n]
                                  + buf0[4096 + v * 256 + n];
                        float tv = __ldg(&g_ssp[2][gr * 256 + n]) + lin - tanhf(lin);
                        t[v][u] = tv;
                        s += tv; s2 += tv * tv;
                    }
#pragma unroll
                    for (int o = 16; o > 0; o >>= 1) {
                        s  += __shfl_xor_sync(0xffffffffu, s,  o);
                        s2 += __shfl_xor_sync(0xffffffffu, s2, o);
                    }
                    if (lane == 0) {
                        sRedLN[v * 8 + 2 * wn + 0] = s;
                        sRedLN[v * 8 + 2 * wn + 1] = s2;
                    }
                }
            }
            __syncthreads();
            if (ws == 0) {
#pragma unroll
                for (int v = 0; v < 8; v++) {
                    int gr = b * 64 + j0 + v;
                    float s  = sRedLN[v * 8 + 0] + sRedLN[v * 8 + 2] + sRedLN[v * 8 + 4] + sRedLN[v * 8 + 6];
                    float s2 = sRedLN[v * 8 + 1] + sRedLN[v * 8 + 3] + sRedLN[v * 8 + 5] + sRedLN[v * 8 + 7];
                    float mean = s * (1.0f / 256.0f);
                    float var  = s2 * (1.0f / 256.0f) - mean * mean;
                    float inv  = rsqrtf(var + 1e-5f);
#pragma unroll
                    for (int u = 0; u < 2; u++) {
                        int n = 64 * wn + 32 * u + lane;
                        float ln = (t[v][u] - mean) * inv;
                        float hv = __ldg(&g_ssp[0][gr * 256 + n]) * ln + __ldg(&g_ssp[1][gr * 256 + n]);
                        sH[v * 256 + n] = fmaxf(hv, 0.0f);
                    }
                }
            }
            __syncthreads();

            // ----- out GEMM: y = tanh(h @ Wout + bout), K=256 (8 chunks) -----
            u64 acc2[8][2];
#pragma unroll
            for (int v = 0; v < 8; v++) { acc2[v][0] = 0ull; acc2[v][1] = 0ull; }
            float4 wreg[4];
#pragma unroll
            for (int q = 0; q < 4; q++) {
                int idx = tid + q * NT, kk = idx >> 6, n4 = idx & 63;
                wreg[q] = __ldg((const float4*)&Wout[kk * 256 + 4 * n4]);
            }
            for (int kc = 0; kc < 8; kc++) {
                __syncthreads();
#pragma unroll
                for (int q = 0; q < 4; q++) {
                    int idx = tid + q * NT, kk = idx >> 6, n4 = idx & 63;
                    *(float4*)&buf0[kk * 256 + 4 * n4] = wreg[q];
                }
                __syncthreads();
                if (kc < 7) {
                    int k0 = (kc + 1) * 32;
#pragma unroll
                    for (int q = 0; q < 4; q++) {
                        int idx = tid + q * NT, kk = idx >> 6, n4 = idx & 63;
                        wreg[q] = __ldg((const float4*)&Wout[(k0 + kk) * 256 + 4 * n4]);
                    }
                }
                gemm_8x2(acc2, buf0, sH, 256, kc * 32, wn, lane, ws);
            }
            __syncthreads();
#pragma unroll
            for (int v = 0; v < 8; v++) { x[v][0] = psum(acc2[v][0]); x[v][1] = psum(acc2[v][1]); }
            if (ws > 0) {
#pragma unroll
                for (int v = 0; v < 8; v++)
#pragma unroll
                    for (int u = 0; u < 2; u++) {
                        int n = 64 * wn + 32 * u + lane;
                        buf0[(ws - 1) * 2048 + v * 256 + n] = x[v][u];
                    }
            }
            __syncthreads();
            if (ws == 0) {
                bool mz = ((64 - st) > g_len[b]);
#pragma unroll
                for (int v = 0; v < 8; v++) {
                    int gr = b * 64 + j0 + v;
#pragma unroll
                    for (int u = 0; u < 2; u++) {
                        int n = 64 * wn + 32 * u + lane;
                        float lin = x[v][u] + buf0[v * 256 + n] + buf0[2048 + v * 256 + n]
                                  + buf0[4096 + v * 256 + n];
                        float yv = tanhf(lin + __ldg(&bout[n]));
                        g_h[gr * 256 + n] = mz ? 0.0f : yv;
                    }
                }
            }
        }
        gsync();
    }

    // =================== final reduction ===================
    if (bid < 16 && tid < 256) {
        float sdot = 0.0f;
        for (int i = 0; i < 64; i++)
            sdot += __ldcg(&g_h[(bid * 64 + i) * 256 + tid]) * __ldg(&root[bid * 64 + i]);
        out[bid * 256 + tid] = sdot;
    }
}

extern "C" void kernel_launch(void* const* d_in, const int* in_sizes, int n_in,
                              void* d_out, int out_size) {
    const int*   tokens = (const int*)  d_in[0];
    const float* A      = (const float*)d_in[1];
    const float* root   = (const float*)d_in[2];
    const float* emb    = (const float*)d_in[3];
    const float* Wp     = (const float*)d_in[4];
    const float* bp     = (const float*)d_in[5];
    const float* W_in   = (const float*)d_in[6];
    const float* b_in   = (const float*)d_in[7];
    const float* Wout   = (const float*)d_in[8];
    const float* bout   = (const float*)d_in[9];
    float* out = (float*)d_out;

    k_reset<<<1, 1>>>();
    k_persist<<<NB, NT>>>(tokens, A, root, emb, Wp, bp, W_in, b_in, Wout, bout, out);
}

// round 11
// speedup vs baseline: 1.8794x; 1.0850x over previous
#include <cuda_runtime.h>
#include <math.h>

#define NB 128
#define NT 512

typedef unsigned long long u64;

// ---------------- device scratch ----------------
__device__ float g_h[1024 * 256];            // carry h (1 MB)
__device__ float g_p[1024 * 8 * 256];        // p[(b*64+i)*8+r][d] (8 MB)
__device__ float g_ssp[3][1024 * 256];       // shift / scale / proj_x
__device__ u64   g_wp2[8][128 * 256];        // Wp pair-packed: [r][k2*256+n] (2 MB)
__device__ u64   g_wo2[128 * 256];           // Wout pair-packed (256 KB)
__device__ int   g_len[16];
__device__ unsigned g_cnt;

// ---------------- f32x2 helpers ----------------
__device__ __forceinline__ void fma2(u64& d, u64 a, u64 b) {
    asm("fma.rn.f32x2 %0, %1, %2, %0;" : "+l"(d) : "l"(a), "l"(b));
}
__device__ __forceinline__ float psum(u64 v) {
    float a, b;
    asm("mov.b64 {%0,%1}, %2;" : "=f"(a), "=f"(b) : "l"(v));
    return a + b;
}
__device__ __forceinline__ u64 pk(float lo, float hi) {
    u64 r;
    asm("mov.b64 %0, {%1,%2};" : "=l"(r) : "f"(lo), "f"(hi));
    return r;
}

// ---------------- grid barrier (128 CTAs, all resident) ----------------
__device__ __forceinline__ void gsync() {
    __syncthreads();
    if (threadIdx.x == 0) {
        __threadfence();
        unsigned ticket = atomicAdd(&g_cnt, 1u);
        unsigned target = (ticket | (NB - 1)) + 1;
        unsigned v;
        do {
            asm volatile("ld.acquire.gpu.u32 %0, [%1];" : "=r"(v) : "l"(&g_cnt) : "memory");
        } while (v < target);
    }
    __syncthreads();
}

__global__ void k_reset() { g_cnt = 0u; }

// ---------------- in_proj micro-kernel (runs once; natural layout + pk) ------
__device__ __forceinline__ void gemm_inproj(u64 (&acc)[8][4], const float* __restrict__ sW,
                                            const float* __restrict__ sX, int wm, int wn, int lane) {
#pragma unroll 2
    for (int kk2 = 0; kk2 < 8; kk2++) {
        const int kb = 4 * kk2;
        u64 wp[4][2];
#pragma unroll
        for (int u = 0; u < 4; u++) {
            int n = 128 * wn + 32 * u + lane;
            wp[u][0] = pk(sW[(kb + 0) * 256 + n], sW[(kb + 1) * 256 + n]);
            wp[u][1] = pk(sW[(kb + 2) * 256 + n], sW[(kb + 3) * 256 + n]);
        }
#pragma unroll
        for (int v = 0; v < 8; v++) {
            float4 af = *(const float4*)&sX[(8 * wm + v) * 32 + kb];
            u64 a01 = pk(af.x, af.y), a23 = pk(af.z, af.w);
#pragma unroll
            for (int u = 0; u < 4; u++) {
                fma2(acc[v][u], a01, wp[u][0]);
                fma2(acc[v][u], a23, wp[u][1]);
            }
        }
    }
}

// ---------------- pair-packed GEMM micro-kernels ----------------
// Phase A: warp = 8 rows x 128 cols; chunk = 32 k2 (64 k). Weights wb: u64[k2][256].
__device__ __forceinline__ void gemmA(u64 (&acc)[8][4], const u64* __restrict__ wb,
                                      const u64* __restrict__ sXu, int kc, int wm, int wn, int lane) {
#pragma unroll 2
    for (int k2p = 0; k2p < 16; k2p++) {
        const int k2 = 2 * k2p;
        u64 wp0[4], wp1[4];
#pragma unroll
        for (int u = 0; u < 4; u++) {
            int n = 128 * wn + 32 * u + lane;
            wp0[u] = wb[k2 * 256 + n];
            wp1[u] = wb[(k2 + 1) * 256 + n];
        }
#pragma unroll
        for (int v = 0; v < 8; v++) {
            ulonglong2 aa = *(const ulonglong2*)&sXu[(8 * wm + v) * 128 + kc * 32 + k2];
#pragma unroll
            for (int u = 0; u < 4; u++) {
                fma2(acc[v][u], aa.x, wp0[u]);
                fma2(acc[v][u], aa.y, wp1[u]);
            }
        }
    }
}

// Phase B: warp = 8 rows x 64 cols x 8-k2 slice (4-way split over ws) of a 32-k2 chunk.
__device__ __forceinline__ void gemmB(u64 (&acc)[8][2], const u64* __restrict__ wb,
                                      const u64* __restrict__ aU, int aStride, int aOff,
                                      int wn, int lane, int ws) {
#pragma unroll
    for (int tp = 0; tp < 4; tp++) {
        const int k2 = ws * 8 + 2 * tp;
        u64 wp00 = wb[k2 * 256 + 64 * wn + lane];
        u64 wp01 = wb[k2 * 256 + 64 * wn + 32 + lane];
        u64 wp10 = wb[(k2 + 1) * 256 + 64 * wn + lane];
        u64 wp11 = wb[(k2 + 1) * 256 + 64 * wn + 32 + lane];
#pragma unroll
        for (int v = 0; v < 8; v++) {
            ulonglong2 aa = *(const ulonglong2*)&aU[v * aStride + aOff + k2];
            fma2(acc[v][0], aa.x, wp00);
            fma2(acc[v][1], aa.x, wp01);
            fma2(acc[v][0], aa.y, wp10);
            fma2(acc[v][1], aa.y, wp11);
        }
    }
}

// dynamic smem float layout:
//  buf[2]  @0      : 2 x 8192 u64 (2 x 64 KB) weight/p double buffer
//  phase A: sXu @32768 (16384 floats = 64x128 u64), sRedA @49152 (256)
//  phase B: sA[2] @32768 (1024), sH @33792 (2048), sRedLN @35840 (64), redK @35904 (6144)
#define SM_FLOATS 49408
#define SMEM_BYTES (SM_FLOATS * 4)

__global__ __launch_bounds__(NT, 1) void k_persist(
    const int*   __restrict__ tokens, const float* __restrict__ A,
    const float* __restrict__ root,   const float* __restrict__ emb,
    const float* __restrict__ Wp,     const float* __restrict__ bp,
    const float* __restrict__ W_in,   const float* __restrict__ b_in,
    const float* __restrict__ Wout,   const float* __restrict__ bout,
    float* __restrict__ out)
{
    extern __shared__ __align__(16) float sm[];
    const int tid = threadIdx.x, lane = tid & 31, w = tid >> 5;
    const int bid = blockIdx.x;

    // =================== prologue ===================
    {   // zero carry: one float4 per thread
        int i = (bid * NT + tid) * 4;
        *(float4*)&g_h[i] = make_float4(0.f, 0.f, 0.f, 0.f);
    }
    if (bid == 0 && tid < 16) {
        int c = 0;
        for (int l = 0; l < 64; l++) c += (tokens[l * 16 + tid] != 0);
        g_len[tid] = c;
    }
    // pack Wp into g_wp2: 262144 u64, 4 per thread
#pragma unroll
    for (int q = 0; q < 4; q++) {
        int idx = (bid * NT + tid) + q * 65536;
        int n = idx & 255, k2 = (idx >> 8) & 127, r = idx >> 15;
        float lo = __ldg(&Wp[(2 * k2) * 2048 + r * 256 + n]);
        float hi = __ldg(&Wp[(2 * k2 + 1) * 2048 + r * 256 + n]);
        g_wp2[r][k2 * 256 + n] = pk(lo, hi);
    }
    // pack Wout into g_wo2: 32768 u64
    {
        int gid = bid * NT + tid;
        if (gid < 32768) {
            int n = gid & 255, k2 = gid >> 8;
            g_wo2[k2 * 256 + n] = pk(__ldg(&Wout[2 * k2 * 256 + n]),
                                     __ldg(&Wout[(2 * k2 + 1) * 256 + n]));
        }
    }
    // in_proj: 48 tiles (3 slots x 16 m-tiles of 64 rows)
    if (bid < 48) {
        const int y = bid >> 4, m0 = (bid & 15) * 64;
        const int wm = w >> 1, wn = w & 1;
        float* sW = sm; float* sX = sm + 8192;
        u64 acc[8][4];
#pragma unroll
        for (int v = 0; v < 8; v++)
#pragma unroll
            for (int u = 0; u < 4; u++) acc[v][u] = 0ull;

        float4 wreg[4], xreg;
#pragma unroll
        for (int q = 0; q < 4; q++) {
            int idx = tid + q * NT, kk = idx >> 6, n4 = idx & 63;
            wreg[q] = __ldg((const float4*)&W_in[kk * 768 + y * 256 + 4 * n4]);
        }
        {
            int m = tid >> 3, k4 = tid & 7, row = m0 + m;
            int tok = __ldg(&tokens[(row & 63) * 16 + (row >> 6)]);
            xreg = __ldg((const float4*)&emb[tok * 256 + 4 * k4]);
        }
        for (int kc = 0; kc < 8; kc++) {
            __syncthreads();
#pragma unroll
            for (int q = 0; q < 4; q++) {
                int idx = tid + q * NT, kk = idx >> 6, n4 = idx & 63;
                *(float4*)&sW[kk * 256 + 4 * n4] = wreg[q];
            }
            { int m = tid >> 3, k4 = tid & 7; *(float4*)&sX[m * 32 + 4 * k4] = xreg; }
            __syncthreads();
            if (kc < 7) {
                int k0 = (kc + 1) * 32;
#pragma unroll
                for (int q = 0; q < 4; q++) {
                    int idx = tid + q * NT, kk = idx >> 6, n4 = idx & 63;
                    wreg[q] = __ldg((const float4*)&W_in[(k0 + kk) * 768 + y * 256 + 4 * n4]);
                }
                int m = tid >> 3, k4 = tid & 7, row = m0 + m;
                int tok = __ldg(&tokens[(row & 63) * 16 + (row >> 6)]);
                xreg = __ldg((const float4*)&emb[tok * 256 + k0 + 4 * k4]);
            }
            gemm_inproj(acc, sW, sX, wm, wn, lane);
        }
#pragma unroll
        for (int v = 0; v < 8; v++) {
            int row = m0 + 8 * wm + v;
#pragma unroll
            for (int u = 0; u < 4; u++) {
                int n = 128 * wn + 32 * u + lane;
                g_ssp[y][row * 256 + n] = psum(acc[v][u]) + __ldg(&b_in[y * 256 + n]);
            }
        }
    }
    gsync();

    // =================== 64 recurrent steps ===================
    for (int st = 0; st < 64; st++) {
        // ---------- phase A: p = LN(h @ Wp_r + bp_r); CTA = 64 rows x one r ----------
        {
            const int m0 = (bid >> 3) * 64;
            const int r  = bid & 7;
            const int wm = w >> 1, wn = w & 1;
            u64* bufu = (u64*)sm;                     // [2][8192]
            u64* sXu  = (u64*)(sm + 32768);           // [64][128]
            float* sRed = sm + 49152;

            // stage full h tile (64 KB), pairs contiguous
            {
                const float4* src = (const float4*)&g_h[m0 * 256];
                float4* dst = (float4*)sXu;
#pragma unroll
                for (int q = 0; q < 8; q++) {
                    int i = tid + q * NT;
                    dst[i] = __ldcg(&src[i]);
                }
            }
            // prefetch W chunk 0 (64 KB), pair-packed contiguous
            const float4* wsrc = (const float4*)&g_wp2[r][0];
            float4 wreg[8];
#pragma unroll
            for (int q = 0; q < 8; q++) wreg[q] = __ldg(&wsrc[q * NT + tid]);

            u64 acc[8][4];
#pragma unroll
            for (int v = 0; v < 8; v++)
#pragma unroll
                for (int u = 0; u < 4; u++) acc[v][u] = 0ull;

            {
                float4* dbuf = (float4*)bufu;
#pragma unroll
                for (int q = 0; q < 8; q++) dbuf[q * NT + tid] = wreg[q];
            }
            __syncthreads();
            for (int kc = 0; kc < 4; kc++) {
                if (kc < 3) {
#pragma unroll
                    for (int q = 0; q < 8; q++)
                        wreg[q] = __ldg(&wsrc[(kc + 1) * 4096 + q * NT + tid]);
                }
                gemmA(acc, bufu + (kc & 1) * 8192, sXu, kc, wm, wn, lane);
                if (kc < 3) {
                    float4* dbuf = (float4*)(bufu + ((kc + 1) & 1) * 8192);
#pragma unroll
                    for (int q = 0; q < 8; q++) dbuf[q * NT + tid] = wreg[q];
                }
                __syncthreads();
            }
            // bias + per-row LayerNorm (row spans 2 wn warps)
            float x[8][4];
#pragma unroll
            for (int v = 0; v < 8; v++) {
                float s = 0.f, s2 = 0.f;
#pragma unroll
                for (int u = 0; u < 4; u++) {
                    int n = 128 * wn + 32 * u + lane;
                    x[v][u] = psum(acc[v][u]) + __ldg(&bp[r * 256 + n]);
                    s  += x[v][u];
                    s2 += x[v][u] * x[v][u];
                }
#pragma unroll
                for (int o = 16; o > 0; o >>= 1) {
                    s  += __shfl_xor_sync(0xffffffffu, s,  o);
                    s2 += __shfl_xor_sync(0xffffffffu, s2, o);
                }
                if (lane == 0) {
                    sRed[(8 * wm + v) * 4 + 2 * wn + 0] = s;
                    sRed[(8 * wm + v) * 4 + 2 * wn + 1] = s2;
                }
            }
            __syncthreads();
#pragma unroll
            for (int v = 0; v < 8; v++) {
                int row = 8 * wm + v;
                float s  = sRed[row * 4 + 0] + sRed[row * 4 + 2];
                float s2 = sRed[row * 4 + 1] + sRed[row * 4 + 3];
                float mean = s * (1.0f / 256.0f);
                float var  = s2 * (1.0f / 256.0f) - mean * mean;
                float inv  = rsqrtf(var + 1e-5f);
#pragma unroll
                for (int u = 0; u < 4; u++) {
                    int n = 128 * wn + 32 * u + lane;
                    g_p[((m0 + row) * 8 + r) * 256 + n] = (x[v][u] - mean) * inv;
                }
            }
        }
        gsync();

        // ---------- phase B: einsum + shrink + LN + gate + outGEMM + tanh + mask ----------
        {
            const int b = bid >> 3, j0 = (bid & 7) * 8;
            const int wn = w & 3, ws = w >> 2;           // 4 col-groups x 4 k-slices
            u64*   bufu   = (u64*)sm;                    // [2][8192]
            float* sAf    = sm + 32768;                  // [2][512]
            float* sH     = sm + 33792;                  // [8][256]
            float* sRedLN = sm + 35840;                  // 64
            float* redK   = sm + 35904;                  // 3 x 2048

            // ----- einsum over K=512: 8 chunks of 64 k (32 k2), pair-packed staging -----
            u64 acc[8][2];
#pragma unroll
            for (int v = 0; v < 8; v++) { acc[v][0] = 0ull; acc[v][1] = 0ull; }

            float2 pr[8][2]; float2 ar = make_float2(0.f, 0.f);
#pragma unroll
            for (int q = 0; q < 8; q++) {
                int sdx = tid + q * NT, k2 = sdx >> 7, nh = sdx & 127;
                const float* base = &g_p[(b * 512 + 2 * k2) * 256 + 2 * nh];
                pr[q][0] = __ldcg((const float2*)base);
                pr[q][1] = __ldcg((const float2*)(base + 256));
            }
            if (tid < 256) {
                int jr = tid >> 5, t = tid & 31;
                int k = 2 * t, i = k >> 3, r = k & 7;
                ar = __ldg((const float2*)&A[((b * 64 + i) * 64 + j0 + jr) * 8 + r]);
            }
            {
                float* d0 = (float*)bufu;
#pragma unroll
                for (int q = 0; q < 8; q++) {
                    int sdx = tid + q * NT, k2 = sdx >> 7, nh = sdx & 127;
                    *(float4*)&d0[(k2 * 256 + 2 * nh) * 2] =
                        make_float4(pr[q][0].x, pr[q][1].x, pr[q][0].y, pr[q][1].y);
                }
                if (tid < 256) *(float2*)&sAf[(tid & 255) * 2] = ar;
            }
            __syncthreads();
            for (int kt = 0; kt < 8; kt++) {
                if (kt < 7) {
#pragma unroll
                    for (int q = 0; q < 8; q++) {
                        int sdx = tid + q * NT, k2 = sdx >> 7, nh = sdx & 127;
                        const float* base = &g_p[(b * 512 + (kt + 1) * 64 + 2 * k2) * 256 + 2 * nh];
                        pr[q][0] = __ldcg((const float2*)base);
                        pr[q][1] = __ldcg((const float2*)(base + 256));
                    }
                    if (tid < 256) {
                        int jr = tid >> 5, t = tid & 31;
                        int k = (kt + 1) * 64 + 2 * t, i = k >> 3, r = k & 7;
                        ar = __ldg((const float2*)&A[((b * 64 + i) * 64 + j0 + jr) * 8 + r]);
                    }
                }
                gemmB(acc, bufu + (kt & 1) * 8192, (const u64*)(sAf + (kt & 1) * 512),
                      32, 0, wn, lane, ws);
                if (kt < 7) {
                    float* dn = (float*)(bufu + ((kt + 1) & 1) * 8192);
#pragma unroll
                    for (int q = 0; q < 8; q++) {
                        int sdx = tid + q * NT, k2 = sdx >> 7, nh = sdx & 127;
                        *(float4*)&dn[(k2 * 256 + 2 * nh) * 2] =
                            make_float4(pr[q][0].x, pr[q][1].x, pr[q][0].y, pr[q][1].y);
                    }
                    if (tid < 256) *(float2*)&sAf[((kt + 1) & 1) * 512 + (tid & 255) * 2] = ar;
                }
                __syncthreads();
            }
            // k-split reduction (ws 1..3 -> redK), then shrink + LN + gate on ws==0
            float x[8][2];
#pragma unroll
            for (int v = 0; v < 8; v++) { x[v][0] = psum(acc[v][0]); x[v][1] = psum(acc[v][1]); }
            if (ws > 0) {
#pragma unroll
                for (int v = 0; v < 8; v++)
#pragma unroll
                    for (int u = 0; u < 2; u++) {
                        int n = 64 * wn + 32 * u + lane;
                        redK[(ws - 1) * 2048 + v * 256 + n] = x[v][u];
                    }
            }
            __syncthreads();
            float t[8][2];
            if (ws == 0) {
#pragma unroll
                for (int v = 0; v < 8; v++) {
                    int gr = b * 64 + j0 + v;
                    float s = 0.f, s2 = 0.f;
#pragma unroll
                    for (int u = 0; u < 2; u++) {
                        int n = 64 * wn + 32 * u + lane;
                        float lin = x[v][u] + redK[v * 256 + n] + redK[2048 + v * 256 + n]
                                  + redK[4096 + v * 256 + n];
                        float tv = __ldg(&g_ssp[2][gr * 256 + n]) + lin - tanhf(lin);
                        t[v][u] = tv;
                        s += tv; s2 += tv * tv;
                    }
#pragma unroll
                    for (int o = 16; o > 0; o >>= 1) {
                        s  += __shfl_xor_sync(0xffffffffu, s,  o);
                        s2 += __shfl_xor_sync(0xffffffffu, s2, o);
                    }
                    if (lane == 0) {
                        sRedLN[v * 8 + 2 * wn + 0] = s;
                        sRedLN[v * 8 + 2 * wn + 1] = s2;
                    }
                }
            }
            __syncthreads();
            if (ws == 0) {
#pragma unroll
                for (int v = 0; v < 8; v++) {
                    int gr = b * 64 + j0 + v;
                    float s  = sRedLN[v * 8 + 0] + sRedLN[v * 8 + 2] + sRedLN[v * 8 + 4] + sRedLN[v * 8 + 6];
                    float s2 = sRedLN[v * 8 + 1] + sRedLN[v * 8 + 3] + sRedLN[v * 8 + 5] + sRedLN[v * 8 + 7];
                    float mean = s * (1.0f / 256.0f);
                    float var  = s2 * (1.0f / 256.0f) - mean * mean;
                    float inv  = rsqrtf(var + 1e-5f);
#pragma unroll
                    for (int u = 0; u < 2; u++) {
                        int n = 64 * wn + 32 * u + lane;
                        float ln = (t[v][u] - mean) * inv;
                        float hv = __ldg(&g_ssp[0][gr * 256 + n]) * ln + __ldg(&g_ssp[1][gr * 256 + n]);
                        sH[v * 256 + n] = fmaxf(hv, 0.0f);
                    }
                }
            }
            __syncthreads();

            // ----- out GEMM: y = tanh(h @ Wout + bout), K=256: 4 chunks of 32 k2 -----
            u64 acc2[8][2];
#pragma unroll
            for (int v = 0; v < 8; v++) { acc2[v][0] = 0ull; acc2[v][1] = 0ull; }
            const float4* wo = (const float4*)g_wo2;
            float4 wreg[8];
#pragma unroll
            for (int q = 0; q < 8; q++) wreg[q] = __ldg(&wo[q * NT + tid]);
            {
                float4* d0 = (float4*)bufu;
#pragma unroll
                for (int q = 0; q < 8; q++) d0[q * NT + tid] = wreg[q];
            }
            __syncthreads();
            for (int kc = 0; kc < 4; kc++) {
                if (kc < 3) {
#pragma unroll
                    for (int q = 0; q < 8; q++)
                        wreg[q] = __ldg(&wo[(kc + 1) * 4096 + q * NT + tid]);
                }
                gemmB(acc2, bufu + (kc & 1) * 8192, (const u64*)sH, 128, kc * 32, wn, lane, ws);
                if (kc < 3) {
                    float4* dn = (float4*)(bufu + ((kc + 1) & 1) * 8192);
#pragma unroll
                    for (int q = 0; q < 8; q++) dn[q * NT + tid] = wreg[q];
                }
                __syncthreads();
            }
#pragma unroll
            for (int v = 0; v < 8; v++) { x[v][0] = psum(acc2[v][0]); x[v][1] = psum(acc2[v][1]); }
            if (ws > 0) {
#pragma unroll
                for (int v = 0; v < 8; v++)
#pragma unroll
                    for (int u = 0; u < 2; u++) {
                        int n = 64 * wn + 32 * u + lane;
                        redK[(ws - 1) * 2048 + v * 256 + n] = x[v][u];
                    }
            }
            __syncthreads();
            if (ws == 0) {
                bool mz = ((64 - st) > g_len[b]);
#pragma unroll
                for (int v = 0; v < 8; v++) {
                    int gr = b * 64 + j0 + v;
#pragma unroll
                    for (int u = 0; u < 2; u++) {
                        int n = 64 * wn + 32 * u + lane;
                        float lin = x[v][u] + redK[v * 256 + n] + redK[2048 + v * 256 + n]
                                  + redK[4096 + v * 256 + n];
                        float yv = tanhf(lin + __ldg(&bout[n]));
                        g_h[gr * 256 + n] = mz ? 0.0f : yv;
                    }
                }
            }
        }
        gsync();
    }

    // =================== final reduction ===================
    if (bid < 16 && tid < 256) {
        float sdot = 0.0f;
        for (int i = 0; i < 64; i++)
            sdot += __ldcg(&g_h[(bid * 64 + i) * 256 + tid]) * __ldg(&root[bid * 64 + i]);
        out[bid * 256 + tid] = sdot;
    }
}

extern "C" void kernel_launch(void* const* d_in, const int* in_sizes, int n_in,
                              void* d_out, int out_size) {
    const int*   tokens = (const int*)  d_in[0];
    const float* A      = (const float*)d_in[1];
    const float* root   = (const float*)d_in[2];
    const float* emb    = (const float*)d_in[3];
    const float* Wp     = (const float*)d_in[4];
    const float* bp     = (const float*)d_in[5];
    const float* W_in   = (const float*)d_in[6];
    const float* b_in   = (const float*)d_in[7];
    const float* Wout   = (const float*)d_in[8];
    const float* bout   = (const float*)d_in[9];
    float* out = (float*)d_out;

    cudaFuncSetAttribute(k_persist, cudaFuncAttributeMaxDynamicSharedMemorySize, SMEM_BYTES);
    k_reset<<<1, 1>>>();
    k_persist<<<NB, NT, SMEM_BYTES>>>(tokens, A, root, emb, Wp, bp, W_in, b_in, Wout, bout, out);
}

// round 12
// speedup vs baseline: 1.9110x; 1.0168x over previous
#include <cuda_runtime.h>
#include <math.h>

#define NB 128
#define NT 512

typedef unsigned long long u64;

// ---------------- device scratch ----------------
__device__ float g_h[1024 * 256];            // carry h (1 MB)
__device__ float g_p[1024 * 8 * 256];        // p[(b*64+i)*8+r][d] (8 MB)
__device__ float g_ssp[3][1024 * 256];       // shift / scale / proj_x
__device__ u64   g_wp2[8][128 * 256];        // Wp pair-packed [r][(k2/2)*512 + n*2 + (k2&1)]
__device__ u64   g_wo2[128 * 256];           // Wout pair-packed [k2][n] (old layout)
__device__ int   g_len[16];
__device__ unsigned g_cnt;                   // global barrier counter (prologue only)
__device__ unsigned g_gcnt[16 * 32];         // per-group counters, 128B apart

// ---------------- f32x2 helpers ----------------
__device__ __forceinline__ void fma2(u64& d, u64 a, u64 b) {
    asm("fma.rn.f32x2 %0, %1, %2, %0;" : "+l"(d) : "l"(a), "l"(b));
}
__device__ __forceinline__ float psum(u64 v) {
    float a, b;
    asm("mov.b64 {%0,%1}, %2;" : "=f"(a), "=f"(b) : "l"(v));
    return a + b;
}
__device__ __forceinline__ u64 pk(float lo, float hi) {
    u64 r;
    asm("mov.b64 %0, {%1,%2};" : "=l"(r) : "f"(lo), "f"(hi));
    return r;
}

// ---------------- barriers (monotonic tickets; no reset needed) ----------------
__device__ __forceinline__ void gsync_all() {
    __syncthreads();
    if (threadIdx.x == 0) {
        __threadfence();
        unsigned ticket = atomicAdd(&g_cnt, 1u);
        unsigned target = (ticket | (NB - 1)) + 1;
        unsigned v;
        do {
            asm volatile("ld.acquire.gpu.u32 %0, [%1];" : "=r"(v) : "l"(&g_cnt) : "memory");
        } while (v < target);
    }
    __syncthreads();
}
__device__ __forceinline__ void gsync_grp(int grp) {
    __syncthreads();
    if (threadIdx.x == 0) {
        __threadfence();
        unsigned* ctr = &g_gcnt[grp * 32];
        unsigned ticket = atomicAdd(ctr, 1u);
        unsigned target = (ticket | 7u) + 1;           // group of 8 CTAs
        unsigned v;
        do {
            asm volatile("ld.acquire.gpu.u32 %0, [%1];" : "=r"(v) : "l"(ctr) : "memory");
        } while (v < target);
    }
    __syncthreads();
}

// ---------------- in_proj micro-kernel (runs once) ----------------
__device__ __forceinline__ void gemm_inproj(u64 (&acc)[8][4], const float* __restrict__ sW,
                                            const float* __restrict__ sX, int wm, int wn, int lane) {
#pragma unroll 2
    for (int kk2 = 0; kk2 < 8; kk2++) {
        const int kb = 4 * kk2;
        u64 wp[4][2];
#pragma unroll
        for (int u = 0; u < 4; u++) {
            int n = 128 * wn + 32 * u + lane;
            wp[u][0] = pk(sW[(kb + 0) * 256 + n], sW[(kb + 1) * 256 + n]);
            wp[u][1] = pk(sW[(kb + 2) * 256 + n], sW[(kb + 3) * 256 + n]);
        }
#pragma unroll
        for (int v = 0; v < 8; v++) {
            float4 af = *(const float4*)&sX[(8 * wm + v) * 32 + kb];
            u64 a01 = pk(af.x, af.y), a23 = pk(af.z, af.w);
#pragma unroll
            for (int u = 0; u < 4; u++) {
                fma2(acc[v][u], a01, wp[u][0]);
                fma2(acc[v][u], a23, wp[u][1]);
            }
        }
    }
}

// ---------------- phase A GEMM: warp = 8 rows x 128 cols, chunk = 32 k2 ----------------
// wb layout: [k2p][256][2] u64 (LDS.128 per fragment gives (k2, k2+1) at col n)
__device__ __forceinline__ void gemmA(u64 (&acc)[8][4], const u64* __restrict__ wb,
                                      const u64* __restrict__ sXu, int kc, int wm, int wn, int lane) {
#pragma unroll 2
    for (int k2p = 0; k2p < 16; k2p++) {
        const u64* wrow = wb + k2p * 512;
        u64 w0[4], w1[4];
#pragma unroll
        for (int u = 0; u < 4; u++) {
            ulonglong2 ww = *(const ulonglong2*)&wrow[(128 * wn + 32 * u + lane) * 2];
            w0[u] = ww.x; w1[u] = ww.y;
        }
#pragma unroll
        for (int v = 0; v < 8; v++) {
            ulonglong2 aa = *(const ulonglong2*)&sXu[(8 * wm + v) * 128 + kc * 32 + 2 * k2p];
#pragma unroll
            for (int u = 0; u < 4; u++) {
                fma2(acc[v][u], aa.x, w0[u]);
                fma2(acc[v][u], aa.y, w1[u]);
            }
        }
    }
}

// ---------------- phase B GEMM: warp = 8 rows x 64 cols x 8-k2 slice (split over ws) ----
// wb layout: [k2][256] u64 (old)
__device__ __forceinline__ void gemmB(u64 (&acc)[8][2], const u64* __restrict__ wb,
                                      const u64* __restrict__ aU, int aStride, int aOff,
                                      int wn, int lane, int ws) {
#pragma unroll
    for (int tp = 0; tp < 4; tp++) {
        const int k2 = ws * 8 + 2 * tp;
        u64 wp00 = wb[k2 * 256 + 64 * wn + lane];
        u64 wp01 = wb[k2 * 256 + 64 * wn + 32 + lane];
        u64 wp10 = wb[(k2 + 1) * 256 + 64 * wn + lane];
        u64 wp11 = wb[(k2 + 1) * 256 + 64 * wn + 32 + lane];
#pragma unroll
        for (int v = 0; v < 8; v++) {
            ulonglong2 aa = *(const ulonglong2*)&aU[v * aStride + aOff + k2];
            fma2(acc[v][0], aa.x, wp00);
            fma2(acc[v][1], aa.x, wp01);
            fma2(acc[v][0], aa.y, wp10);
            fma2(acc[v][1], aa.y, wp11);
        }
    }
}

// dynamic smem float layout:
//  bufu[2] @0 (32768 floats = 2x8192 u64)
//  phase A: sXu @32768 (16384), sRedA @49152 (256)
//  phase B: sAf @32768 (1024), sH @33792 (2048), sRedLN @35840 (64), redK @35904 (4x2048)
#define SM_FLOATS 49408
#define SMEM_BYTES (SM_FLOATS * 4)

__global__ __launch_bounds__(NT, 1) void k_persist(
    const int*   __restrict__ tokens, const float* __restrict__ A,
    const float* __restrict__ root,   const float* __restrict__ emb,
    const float* __restrict__ Wp,     const float* __restrict__ bp,
    const float* __restrict__ W_in,   const float* __restrict__ b_in,
    const float* __restrict__ Wout,   const float* __restrict__ bout,
    float* __restrict__ out)
{
    extern __shared__ __align__(16) float sm[];
    const int tid = threadIdx.x, lane = tid & 31, w = tid >> 5;
    const int bid = blockIdx.x;
    const int grp = bid >> 3;                 // batch group (16 groups x 8 CTAs)

    // =================== prologue ===================
    {   // zero carry: one float4 per thread
        int i = (bid * NT + tid) * 4;
        *(float4*)&g_h[i] = make_float4(0.f, 0.f, 0.f, 0.f);
    }
    if (bid == 0 && tid < 16) {
        int c = 0;
        for (int l = 0; l < 64; l++) c += (tokens[l * 16 + tid] != 0);
        g_len[tid] = c;
    }
    // pack Wp into g_wp2 (paired layout): 262144 u64, 4 per thread
#pragma unroll
    for (int q = 0; q < 4; q++) {
        int idx = (bid * NT + tid) + q * 65536;
        int n = idx & 255, k2 = (idx >> 8) & 127, r = idx >> 15;
        float lo = __ldg(&Wp[(2 * k2) * 2048 + r * 256 + n]);
        float hi = __ldg(&Wp[(2 * k2 + 1) * 2048 + r * 256 + n]);
        g_wp2[r][(k2 >> 1) * 512 + n * 2 + (k2 & 1)] = pk(lo, hi);
    }
    // pack Wout into g_wo2 (old layout)
    {
        int gid = bid * NT + tid;
        if (gid < 32768) {
            int n = gid & 255, k2 = gid >> 8;
            g_wo2[k2 * 256 + n] = pk(__ldg(&Wout[2 * k2 * 256 + n]),
                                     __ldg(&Wout[(2 * k2 + 1) * 256 + n]));
        }
    }
    // in_proj: 48 tiles (3 slots x 16 m-tiles of 64 rows)
    if (bid < 48) {
        const int y = bid >> 4, m0 = (bid & 15) * 64;
        const int wm = w >> 1, wn = w & 1;
        float* sW = sm; float* sX = sm + 8192;
        u64 acc[8][4];
#pragma unroll
        for (int v = 0; v < 8; v++)
#pragma unroll
            for (int u = 0; u < 4; u++) acc[v][u] = 0ull;

        float4 wreg[4], xreg;
#pragma unroll
        for (int q = 0; q < 4; q++) {
            int idx = tid + q * NT, kk = idx >> 6, n4 = idx & 63;
            wreg[q] = __ldg((const float4*)&W_in[kk * 768 + y * 256 + 4 * n4]);
        }
        {
            int m = tid >> 3, k4 = tid & 7, row = m0 + m;
            int tok = __ldg(&tokens[(row & 63) * 16 + (row >> 6)]);
            xreg = __ldg((const float4*)&emb[tok * 256 + 4 * k4]);
        }
        for (int kc = 0; kc < 8; kc++) {
            __syncthreads();
#pragma unroll
            for (int q = 0; q < 4; q++) {
                int idx = tid + q * NT, kk = idx >> 6, n4 = idx & 63;
                *(float4*)&sW[kk * 256 + 4 * n4] = wreg[q];
            }
            { int m = tid >> 3, k4 = tid & 7; *(float4*)&sX[m * 32 + 4 * k4] = xreg; }
            __syncthreads();
            if (kc < 7) {
                int k0 = (kc + 1) * 32;
#pragma unroll
                for (int q = 0; q < 4; q++) {
                    int idx = tid + q * NT, kk = idx >> 6, n4 = idx & 63;
                    wreg[q] = __ldg((const float4*)&W_in[(k0 + kk) * 768 + y * 256 + 4 * n4]);
                }
                int m = tid >> 3, k4 = tid & 7, row = m0 + m;
                int tok = __ldg(&tokens[(row & 63) * 16 + (row >> 6)]);
                xreg = __ldg((const float4*)&emb[tok * 256 + k0 + 4 * k4]);
            }
            gemm_inproj(acc, sW, sX, wm, wn, lane);
        }
#pragma unroll
        for (int v = 0; v < 8; v++) {
            int row = m0 + 8 * wm + v;
#pragma unroll
            for (int u = 0; u < 4; u++) {
                int n = 128 * wn + 32 * u + lane;
                g_ssp[y][row * 256 + n] = psum(acc[v][u]) + __ldg(&b_in[y * 256 + n]);
            }
        }
    }
    gsync_all();

    // =================== 64 recurrent steps (per-group pipeline) ===================
    for (int st = 0; st < 64; st++) {
        // ---------- phase A: p = LN(h @ Wp_r + bp_r); CTA = 64 rows (batch grp) x r ----------
        {
            const int m0 = grp * 64;
            const int r  = bid & 7;
            const int wm = w >> 1, wn = w & 1;
            u64* bufu = (u64*)sm;                     // [2][8192]
            u64* sXu  = (u64*)(sm + 32768);           // [64][128]
            float* sRed = sm + 49152;

            // stage full h tile (64 KB), pairs contiguous
            {
                const float4* src = (const float4*)&g_h[m0 * 256];
                float4* dst = (float4*)sXu;
#pragma unroll
                for (int q = 0; q < 8; q++) {
                    int i = tid + q * NT;
                    dst[i] = __ldcg(&src[i]);
                }
            }
            const float4* wsrc = (const float4*)&g_wp2[r][0];
            float4 wreg[8];
#pragma unroll
            for (int q = 0; q < 8; q++) wreg[q] = __ldg(&wsrc[q * NT + tid]);

            u64 acc[8][4];
#pragma unroll
            for (int v = 0; v < 8; v++)
#pragma unroll
                for (int u = 0; u < 4; u++) acc[v][u] = 0ull;

            {
                float4* dbuf = (float4*)bufu;
#pragma unroll
                for (int q = 0; q < 8; q++) dbuf[q * NT + tid] = wreg[q];
            }
            __syncthreads();
            for (int kc = 0; kc < 4; kc++) {
                if (kc < 3) {
#pragma unroll
                    for (int q = 0; q < 8; q++)
                        wreg[q] = __ldg(&wsrc[(kc + 1) * 4096 + q * NT + tid]);
                }
                gemmA(acc, bufu + (kc & 1) * 8192, sXu, kc, wm, wn, lane);
                if (kc < 3) {
                    float4* dbuf = (float4*)(bufu + ((kc + 1) & 1) * 8192);
#pragma unroll
                    for (int q = 0; q < 8; q++) dbuf[q * NT + tid] = wreg[q];
                }
                __syncthreads();
            }
            // bias + per-row LayerNorm (row spans 2 wn warps)
            float bpv[4];
#pragma unroll
            for (int u = 0; u < 4; u++) bpv[u] = __ldg(&bp[r * 256 + 128 * wn + 32 * u + lane]);
            float x[8][4];
#pragma unroll
            for (int v = 0; v < 8; v++) {
                float s = 0.f, s2 = 0.f;
#pragma unroll
                for (int u = 0; u < 4; u++) {
                    x[v][u] = psum(acc[v][u]) + bpv[u];
                    s  += x[v][u];
                    s2 += x[v][u] * x[v][u];
                }
#pragma unroll
                for (int o = 16; o > 0; o >>= 1) {
                    s  += __shfl_xor_sync(0xffffffffu, s,  o);
                    s2 += __shfl_xor_sync(0xffffffffu, s2, o);
                }
                if (lane == 0) {
                    sRed[(8 * wm + v) * 4 + 2 * wn + 0] = s;
                    sRed[(8 * wm + v) * 4 + 2 * wn + 1] = s2;
                }
            }
            __syncthreads();
#pragma unroll
            for (int v = 0; v < 8; v++) {
                int row = 8 * wm + v;
                float s  = sRed[row * 4 + 0] + sRed[row * 4 + 2];
                float s2 = sRed[row * 4 + 1] + sRed[row * 4 + 3];
                float mean = s * (1.0f / 256.0f);
                float var  = s2 * (1.0f / 256.0f) - mean * mean;
                float inv  = rsqrtf(var + 1e-5f);
#pragma unroll
                for (int u = 0; u < 4; u++) {
                    int n = 128 * wn + 32 * u + lane;
                    g_p[((m0 + row) * 8 + r) * 256 + n] = (x[v][u] - mean) * inv;
                }
            }
        }
        gsync_grp(grp);

        // ---------- phase B: einsum + shrink + LN + gate + outGEMM + tanh + mask ----------
        {
            const int b = grp, j0 = (bid & 7) * 8;
            const int wn = w & 3, ws = w >> 2;           // 4 col-groups x 4 k-slices
            u64*   bufu   = (u64*)sm;                    // [2][8192]
            float* sAf    = sm + 32768;                  // [2][512]
            float* sH     = sm + 33792;                  // [8][256]
            float* sRedLN = sm + 35840;                  // 64
            float* redK   = sm + 35904;                  // [4][2048]

            // ----- einsum over K=512: 8 chunks of 64 k (32 k2) -----
            u64 acc[8][2];
#pragma unroll
            for (int v = 0; v < 8; v++) { acc[v][0] = 0ull; acc[v][1] = 0ull; }

            float2 pr[8][2]; float2 ar = make_float2(0.f, 0.f);
#pragma unroll
            for (int q = 0; q < 8; q++) {
                int sdx = tid + q * NT, k2 = sdx >> 7, nh = sdx & 127;
                const float* base = &g_p[(b * 512 + 2 * k2) * 256 + 2 * nh];
                pr[q][0] = __ldcg((const float2*)base);
                pr[q][1] = __ldcg((const float2*)(base + 256));
            }
            if (tid < 256) {
                int jr = tid >> 5, t = tid & 31;
                int k = 2 * t, i = k >> 3, r = k & 7;
                ar = __ldg((const float2*)&A[((b * 64 + i) * 64 + j0 + jr) * 8 + r]);
            }
            {
                float* d0 = (float*)bufu;
#pragma unroll
                for (int q = 0; q < 8; q++) {
                    int sdx = tid + q * NT, k2 = sdx >> 7, nh = sdx & 127;
                    *(float4*)&d0[(k2 * 256 + 2 * nh) * 2] =
                        make_float4(pr[q][0].x, pr[q][1].x, pr[q][0].y, pr[q][1].y);
                }
                if (tid < 256) *(float2*)&sAf[(tid & 255) * 2] = ar;
            }
            __syncthreads();
            for (int kt = 0; kt < 8; kt++) {
                if (kt < 7) {
#pragma unroll
                    for (int q = 0; q < 8; q++) {
                        int sdx = tid + q * NT, k2 = sdx >> 7, nh = sdx & 127;
                        const float* base = &g_p[(b * 512 + (kt + 1) * 64 + 2 * k2) * 256 + 2 * nh];
                        pr[q][0] = __ldcg((const float2*)base);
                        pr[q][1] = __ldcg((const float2*)(base + 256));
                    }
                    if (tid < 256) {
                        int jr = tid >> 5, t = tid & 31;
                        int k = (kt + 1) * 64 + 2 * t, i = k >> 3, r = k & 7;
                        ar = __ldg((const float2*)&A[((b * 64 + i) * 64 + j0 + jr) * 8 + r]);
                    }
                }
                gemmB(acc, bufu + (kt & 1) * 8192, (const u64*)(sAf + (kt & 1) * 512),
                      32, 0, wn, lane, ws);
                if (kt < 7) {
                    float* dn = (float*)(bufu + ((kt + 1) & 1) * 8192);
#pragma unroll
                    for (int q = 0; q < 8; q++) {
                        int sdx = tid + q * NT, k2 = sdx >> 7, nh = sdx & 127;
                        *(float4*)&dn[(k2 * 256 + 2 * nh) * 2] =
                            make_float4(pr[q][0].x, pr[q][1].x, pr[q][0].y, pr[q][1].y);
                    }
                    if (tid < 256) *(float2*)&sAf[((kt + 1) & 1) * 512 + (tid & 255) * 2] = ar;
                }
                __syncthreads();
            }
            // ----- epilogue 1 (parallel over all 16 warps) -----
#pragma unroll
            for (int v = 0; v < 8; v++)
#pragma unroll
                for (int u = 0; u < 2; u++) {
                    int n = 64 * wn + 32 * u + lane;
                    redK[ws * 2048 + v * 256 + n] = psum(acc[v][u]);
                }
            __syncthreads();
            {
                const int v = w >> 1, ch = w & 1, gr = b * 64 + j0 + v;
                float t4[4], s = 0.f, s2 = 0.f;
#pragma unroll
                for (int u = 0; u < 4; u++) {
                    int n = ch * 128 + 32 * u + lane;
                    float lin = redK[v * 256 + n] + redK[2048 + v * 256 + n]
                              + redK[4096 + v * 256 + n] + redK[6144 + v * 256 + n];
                    float tv = __ldg(&g_ssp[2][gr * 256 + n]) + lin - tanhf(lin);
                    t4[u] = tv;
                    s += tv; s2 += tv * tv;
                }
#pragma unroll
                for (int o = 16; o > 0; o >>= 1) {
                    s  += __shfl_xor_sync(0xffffffffu, s,  o);
                    s2 += __shfl_xor_sync(0xffffffffu, s2, o);
                }
                if (lane == 0) {
                    sRedLN[v * 4 + 2 * ch + 0] = s;
                    sRedLN[v * 4 + 2 * ch + 1] = s2;
                }
                __syncthreads();
                float ts  = sRedLN[v * 4 + 0] + sRedLN[v * 4 + 2];
                float ts2 = sRedLN[v * 4 + 1] + sRedLN[v * 4 + 3];
                float mean = ts * (1.0f / 256.0f);
                float var  = ts2 * (1.0f / 256.0f) - mean * mean;
                float inv  = rsqrtf(var + 1e-5f);
#pragma unroll
                for (int u = 0; u < 4; u++) {
                    int n = ch * 128 + 32 * u + lane;
                    float ln = (t4[u] - mean) * inv;
                    float hv = __ldg(&g_ssp[0][gr * 256 + n]) * ln + __ldg(&g_ssp[1][gr * 256 + n]);
                    sH[v * 256 + n] = fmaxf(hv, 0.0f);
                }
            }
            __syncthreads();

            // ----- out GEMM: K=256: 4 chunks of 32 k2 -----
            u64 acc2[8][2];
#pragma unroll
            for (int v = 0; v < 8; v++) { acc2[v][0] = 0ull; acc2[v][1] = 0ull; }
            const float4* wo = (const float4*)g_wo2;
            float4 wreg[8];
#pragma unroll
            for (int q = 0; q < 8; q++) wreg[q] = __ldg(&wo[q * NT + tid]);
            {
                float4* d0 = (float4*)bufu;
#pragma unroll
                for (int q = 0; q < 8; q++) d0[q * NT + tid] = wreg[q];
            }
            __syncthreads();
            for (int kc = 0; kc < 4; kc++) {
                if (kc < 3) {
#pragma unroll
                    for (int q = 0; q < 8; q++)
                        wreg[q] = __ldg(&wo[(kc + 1) * 4096 + q * NT + tid]);
                }
                gemmB(acc2, bufu + (kc & 1) * 8192, (const u64*)sH, 128, kc * 32, wn, lane, ws);
                if (kc < 3) {
                    float4* dn = (float4*)(bufu + ((kc + 1) & 1) * 8192);
#pragma unroll
                    for (int q = 0; q < 8; q++) dn[q * NT + tid] = wreg[q];
                }
                __syncthreads();
            }
            // ----- epilogue 2 (parallel over all 16 warps) -----
#pragma unroll
            for (int v = 0; v < 8; v++)
#pragma unroll
                for (int u = 0; u < 2; u++) {
                    int n = 64 * wn + 32 * u + lane;
                    redK[ws * 2048 + v * 256 + n] = psum(acc2[v][u]);
                }
            __syncthreads();
            {
                const int v = w >> 1, ch = w & 1, gr = b * 64 + j0 + v;
                bool mz = ((64 - st) > g_len[b]);
#pragma unroll
                for (int u = 0; u < 4; u++) {
                    int n = ch * 128 + 32 * u + lane;
                    float lin = redK[v * 256 + n] + redK[2048 + v * 256 + n]
                              + redK[4096 + v * 256 + n] + redK[6144 + v * 256 + n]
                              + __ldg(&bout[n]);
                    float yv = tanhf(lin);
                    g_h[gr * 256 + n] = mz ? 0.0f : yv;
                }
            }
        }
        gsync_grp(grp);
    }

    // =================== final reduction (group leader CTA) ===================
    if ((bid & 7) == 0 && tid < 256) {
        float sdot = 0.0f;
        for (int i = 0; i < 64; i++)
            sdot += __ldcg(&g_h[(grp * 64 + i) * 256 + tid]) * __ldg(&root[grp * 64 + i]);
        out[grp * 256 + tid] = sdot;
    }
}

extern "C" void kernel_launch(void* const* d_in, const int* in_sizes, int n_in,
                              void* d_out, int out_size) {
    const int*   tokens = (const int*)  d_in[0];
    const float* A      = (const float*)d_in[1];
    const float* root   = (const float*)d_in[2];
    const float* emb    = (const float*)d_in[3];
    const float* Wp     = (const float*)d_in[4];
    const float* bp     = (const float*)d_in[5];
    const float* W_in   = (const float*)d_in[6];
    const float* b_in   = (const float*)d_in[7];
    const float* Wout   = (const float*)d_in[8];
    const float* bout   = (const float*)d_in[9];
    float* out = (float*)d_out;

    cudaFuncSetAttribute(k_persist, cudaFuncAttributeMaxDynamicSharedMemorySize, SMEM_BYTES);
    k_persist<<<NB, NT, SMEM_BYTES>>>(tokens, A, root, emb, Wp, bp, W_in, b_in, Wout, bout, out);
}

// round 13
// speedup vs baseline: 2.0802x; 1.0886x over previous
#include <cuda_runtime.h>
#include <math.h>

#define NB 128
#define NT 512

typedef unsigned long long u64;

// ---------------- device scratch ----------------
__device__ float g_h[1024 * 256];            // carry h (1 MB)
__device__ float g_p[1024 * 8 * 256];        // reused as lin partials [grp*8+r][64 j][256 d]
__device__ float g_ssp[3][1024 * 256];       // shift / scale / proj_x
__device__ u64   g_wp2[8][128 * 256];        // Wp pair-packed [r][(k2/2)*512 + n*2 + (k2&1)]
__device__ u64   g_wo2[128 * 256];           // Wout pair-packed [k2][n]
__device__ int   g_len[16];
__device__ unsigned g_cnt;                   // global barrier counter (prologue only)
__device__ unsigned g_gcnt[16 * 32];         // per-group counters, 128B apart

// ---------------- f32x2 helpers ----------------
__device__ __forceinline__ void fma2(u64& d, u64 a, u64 b) {
    asm("fma.rn.f32x2 %0, %1, %2, %0;" : "+l"(d) : "l"(a), "l"(b));
}
__device__ __forceinline__ float psum(u64 v) {
    float a, b;
    asm("mov.b64 {%0,%1}, %2;" : "=f"(a), "=f"(b) : "l"(v));
    return a + b;
}
__device__ __forceinline__ u64 pk(float lo, float hi) {
    u64 r;
    asm("mov.b64 %0, {%1,%2};" : "=l"(r) : "f"(lo), "f"(hi));
    return r;
}

// ---------------- barriers (monotonic tickets) ----------------
__device__ __forceinline__ void gsync_all() {
    __syncthreads();
    if (threadIdx.x == 0) {
        __threadfence();
        unsigned ticket = atomicAdd(&g_cnt, 1u);
        unsigned target = (ticket | (NB - 1)) + 1;
        unsigned v;
        do {
            asm volatile("ld.acquire.gpu.u32 %0, [%1];" : "=r"(v) : "l"(&g_cnt) : "memory");
        } while (v < target);
    }
    __syncthreads();
}
__device__ __forceinline__ void gsync_grp(int grp) {
    __syncthreads();
    if (threadIdx.x == 0) {
        __threadfence();
        unsigned* ctr = &g_gcnt[grp * 32];
        unsigned ticket = atomicAdd(ctr, 1u);
        unsigned target = (ticket | 7u) + 1;           // group of 8 CTAs
        unsigned v;
        do {
            asm volatile("ld.acquire.gpu.u32 %0, [%1];" : "=r"(v) : "l"(ctr) : "memory");
        } while (v < target);
    }
    __syncthreads();
}

// ---------------- in_proj micro-kernel (runs once) ----------------
__device__ __forceinline__ void gemm_inproj(u64 (&acc)[8][4], const float* __restrict__ sW,
                                            const float* __restrict__ sX, int wm, int wn, int lane) {
#pragma unroll 2
    for (int kk2 = 0; kk2 < 8; kk2++) {
        const int kb = 4 * kk2;
        u64 wp[4][2];
#pragma unroll
        for (int u = 0; u < 4; u++) {
            int n = 128 * wn + 32 * u + lane;
            wp[u][0] = pk(sW[(kb + 0) * 256 + n], sW[(kb + 1) * 256 + n]);
            wp[u][1] = pk(sW[(kb + 2) * 256 + n], sW[(kb + 3) * 256 + n]);
        }
#pragma unroll
        for (int v = 0; v < 8; v++) {
            float4 af = *(const float4*)&sX[(8 * wm + v) * 32 + kb];
            u64 a01 = pk(af.x, af.y), a23 = pk(af.z, af.w);
#pragma unroll
            for (int u = 0; u < 4; u++) {
                fma2(acc[v][u], a01, wp[u][0]);
                fma2(acc[v][u], a23, wp[u][1]);
            }
        }
    }
}

// ---------------- phase A GEMM: warp = 8 rows x 128 cols; half-chunk = 8 k2p (16 k2) ----
// wb layout: [k2p][256][2] u64 (LDS.128 fragment -> (k2, k2+1) at col n)
__device__ __forceinline__ void gemmA_half(u64 (&acc)[8][4], const u64* __restrict__ wb,
                                           const u64* __restrict__ sXu, int hc,
                                           int wm, int wn, int lane) {
#pragma unroll 2
    for (int k2p = 0; k2p < 8; k2p++) {
        const u64* wrow = wb + k2p * 512;
        u64 w0[4], w1[4];
#pragma unroll
        for (int u = 0; u < 4; u++) {
            ulonglong2 ww = *(const ulonglong2*)&wrow[(128 * wn + 32 * u + lane) * 2];
            w0[u] = ww.x; w1[u] = ww.y;
        }
#pragma unroll
        for (int v = 0; v < 8; v++) {
            ulonglong2 aa = *(const ulonglong2*)&sXu[(8 * wm + v) * 128 + hc * 16 + 2 * k2p];
#pragma unroll
            for (int u = 0; u < 4; u++) {
                fma2(acc[v][u], aa.x, w0[u]);
                fma2(acc[v][u], aa.y, w1[u]);
            }
        }
    }
}

// ---------------- phase B out-GEMM: warp = 8 rows x 64 cols x 8-k2 slice (split over ws) ----
__device__ __forceinline__ void gemmB(u64 (&acc)[8][2], const u64* __restrict__ wb,
                                      const u64* __restrict__ aU, int aStride, int aOff,
                                      int wn, int lane, int ws) {
#pragma unroll
    for (int tp = 0; tp < 4; tp++) {
        const int k2 = ws * 8 + 2 * tp;
        u64 wp00 = wb[k2 * 256 + 64 * wn + lane];
        u64 wp01 = wb[k2 * 256 + 64 * wn + 32 + lane];
        u64 wp10 = wb[(k2 + 1) * 256 + 64 * wn + lane];
        u64 wp11 = wb[(k2 + 1) * 256 + 64 * wn + 32 + lane];
#pragma unroll
        for (int v = 0; v < 8; v++) {
            ulonglong2 aa = *(const ulonglong2*)&aU[v * aStride + aOff + k2];
            fma2(acc[v][0], aa.x, wp00);
            fma2(acc[v][1], aa.x, wp01);
            fma2(acc[v][0], aa.y, wp10);
            fma2(acc[v][1], aa.y, wp11);
        }
    }
}

// dynamic smem float layout (byte offsets are 4x):
//  phase A: sW[2]  @0      (16384 = 2 x 4096 u64, 2 x 32KB weight halves)
//           sXu    @16384  (16384 = 64 rows x 128 k2 u64, h tile)
//           sP4    @32768  (16384 = 16 i4 x 512 u64, LN(p) quad-packed)
//           As4    @49152  (4096  = 16 i4 x 64 j u128, persistent A slice)
//           sRedA  @53248  (256)
//  phase B: bufu[2]@0      (32768 = 2 x 8192 u64 Wout staging)
//           sH     @32768  (2048), sRedLN @34816 (64), redK @34880 (8192)
#define SM_FLOATS 53504
#define SMEM_BYTES (SM_FLOATS * 4)

__global__ __launch_bounds__(NT, 1) void k_persist(
    const int*   __restrict__ tokens, const float* __restrict__ A,
    const float* __restrict__ root,   const float* __restrict__ emb,
    const float* __restrict__ Wp,     const float* __restrict__ bp,
    const float* __restrict__ W_in,   const float* __restrict__ b_in,
    const float* __restrict__ Wout,   const float* __restrict__ bout,
    float* __restrict__ out)
{
    extern __shared__ __align__(16) float sm[];
    const int tid = threadIdx.x, lane = tid & 31, w = tid >> 5;
    const int bid = blockIdx.x;
    const int grp = bid >> 3;                 // batch group (16 groups x 8 CTAs)
    const int r   = bid & 7;                  // this CTA's relation / j-chunk id

    // =================== prologue ===================
    {   // zero carry: one float4 per thread
        int i = (bid * NT + tid) * 4;
        *(float4*)&g_h[i] = make_float4(0.f, 0.f, 0.f, 0.f);
    }
    if (bid == 0 && tid < 16) {
        int c = 0;
        for (int l = 0; l < 64; l++) c += (tokens[l * 16 + tid] != 0);
        g_len[tid] = c;
    }
    // pack Wp into g_wp2 (paired layout): 262144 u64, 4 per thread
#pragma unroll
    for (int q = 0; q < 4; q++) {
        int idx = (bid * NT + tid) + q * 65536;
        int n = idx & 255, k2 = (idx >> 8) & 127, rr = idx >> 15;
        float lo = __ldg(&Wp[(2 * k2) * 2048 + rr * 256 + n]);
        float hi = __ldg(&Wp[(2 * k2 + 1) * 2048 + rr * 256 + n]);
        g_wp2[rr][(k2 >> 1) * 512 + n * 2 + (k2 & 1)] = pk(lo, hi);
    }
    // pack Wout into g_wo2
    {
        int gid = bid * NT + tid;
        if (gid < 32768) {
            int n = gid & 255, k2 = gid >> 8;
            g_wo2[k2 * 256 + n] = pk(__ldg(&Wout[2 * k2 * 256 + n]),
                                     __ldg(&Wout[(2 * k2 + 1) * 256 + n]));
        }
    }
    // in_proj: 48 tiles (3 slots x 16 m-tiles of 64 rows)
    if (bid < 48) {
        const int y = bid >> 4, m0 = (bid & 15) * 64;
        const int wm = w >> 1, wn = w & 1;
        float* sW = sm; float* sX = sm + 8192;
        u64 acc[8][4];
#pragma unroll
        for (int v = 0; v < 8; v++)
#pragma unroll
            for (int u = 0; u < 4; u++) acc[v][u] = 0ull;

        float4 wreg[4], xreg;
#pragma unroll
        for (int q = 0; q < 4; q++) {
            int idx = tid + q * NT, kk = idx >> 6, n4 = idx & 63;
            wreg[q] = __ldg((const float4*)&W_in[kk * 768 + y * 256 + 4 * n4]);
        }
        {
            int m = tid >> 3, k4 = tid & 7, row = m0 + m;
            int tok = __ldg(&tokens[(row & 63) * 16 + (row >> 6)]);
            xreg = __ldg((const float4*)&emb[tok * 256 + 4 * k4]);
        }
        for (int kc = 0; kc < 8; kc++) {
            __syncthreads();
#pragma unroll
            for (int q = 0; q < 4; q++) {
                int idx = tid + q * NT, kk = idx >> 6, n4 = idx & 63;
                *(float4*)&sW[kk * 256 + 4 * n4] = wreg[q];
            }
            { int m = tid >> 3, k4 = tid & 7; *(float4*)&sX[m * 32 + 4 * k4] = xreg; }
            __syncthreads();
            if (kc < 7) {
                int k0 = (kc + 1) * 32;
#pragma unroll
                for (int q = 0; q < 4; q++) {
                    int idx = tid + q * NT, kk = idx >> 6, n4 = idx & 63;
                    wreg[q] = __ldg((const float4*)&W_in[(k0 + kk) * 768 + y * 256 + 4 * n4]);
                }
                int m = tid >> 3, k4 = tid & 7, row = m0 + m;
                int tok = __ldg(&tokens[(row & 63) * 16 + (row >> 6)]);
                xreg = __ldg((const float4*)&emb[tok * 256 + k0 + 4 * k4]);
            }
            gemm_inproj(acc, sW, sX, wm, wn, lane);
        }
#pragma unroll
        for (int v = 0; v < 8; v++) {
            int row = m0 + 8 * wm + v;
#pragma unroll
            for (int u = 0; u < 4; u++) {
                int n = 128 * wn + 32 * u + lane;
                g_ssp[y][row * 256 + n] = psum(acc[v][u]) + __ldg(&b_in[y * 256 + n]);
            }
        }
    }
    gsync_all();

    // ---- persistent A slice for this CTA's relation r: As4[i4][j] (16KB, untouched by phase B) ----
    {
        ulonglong2* As4 = (ulonglong2*)(sm + 49152);
#pragma unroll
        for (int qq = 0; qq < 2; qq++) {
            int i4 = (tid >> 6) + 8 * qq, j = tid & 63;
            float a0 = __ldg(&A[((grp * 64 + 4 * i4 + 0) * 64 + j) * 8 + r]);
            float a1 = __ldg(&A[((grp * 64 + 4 * i4 + 1) * 64 + j) * 8 + r]);
            float a2 = __ldg(&A[((grp * 64 + 4 * i4 + 2) * 64 + j) * 8 + r]);
            float a3 = __ldg(&A[((grp * 64 + 4 * i4 + 3) * 64 + j) * 8 + r]);
            ulonglong2 t; t.x = pk(a0, a1); t.y = pk(a2, a3);
            As4[i4 * 64 + j] = t;
        }
    }

    // =================== 64 recurrent steps (per-group pipeline) ===================
    for (int st = 0; st < 64; st++) {
        // ---------- phase A: p = LN(h @ Wp_r + bp_r) in smem, then r-partial einsum ----------
        {
            const int m0 = grp * 64;
            const int wm = w >> 1, wn = w & 1;
            u64* sW  = (u64*)sm;                           // [2][4096]
            u64* sXu = (u64*)(sm + 16384);                 // [64][128]
            u64* sP4 = (u64*)(sm + 32768);                 // [16][512]
            const ulonglong2* As4 = (const ulonglong2*)(sm + 49152);
            float* sRedA = sm + 53248;

            // stage h tile (64 KB)
            {
                const float4* src = (const float4*)&g_h[m0 * 256];
                float4* dst = (float4*)sXu;
#pragma unroll
                for (int q = 0; q < 8; q++) {
                    int i = tid + q * NT;
                    dst[i] = __ldcg(&src[i]);
                }
            }
            // weight half-chunk 0 prefetch + store
            const float4* wsrc = (const float4*)&g_wp2[r][0];
            float4 wreg[4];
#pragma unroll
            for (int q = 0; q < 4; q++) wreg[q] = __ldg(&wsrc[q * NT + tid]);
            {
                float4* d0 = (float4*)sW;
#pragma unroll
                for (int q = 0; q < 4; q++) d0[q * NT + tid] = wreg[q];
            }
            __syncthreads();

            u64 acc[8][4];
#pragma unroll
            for (int v = 0; v < 8; v++)
#pragma unroll
                for (int u = 0; u < 4; u++) acc[v][u] = 0ull;

            for (int hc = 0; hc < 8; hc++) {
                if (hc < 7) {
#pragma unroll
                    for (int q = 0; q < 4; q++)
                        wreg[q] = __ldg(&wsrc[(hc + 1) * 2048 + q * NT + tid]);
                }
                gemmA_half(acc, sW + (hc & 1) * 4096, sXu, hc, wm, wn, lane);
                if (hc < 7) {
                    float4* dn = (float4*)(sW + ((hc + 1) & 1) * 4096);
#pragma unroll
                    for (int q = 0; q < 4; q++) dn[q * NT + tid] = wreg[q];
                }
                __syncthreads();
            }
            // bias + per-row LayerNorm (row spans 2 wn warps)
            float bpv[4];
#pragma unroll
            for (int u = 0; u < 4; u++) bpv[u] = __ldg(&bp[r * 256 + 128 * wn + 32 * u + lane]);
            float x[8][4];
#pragma unroll
            for (int v = 0; v < 8; v++) {
                float s = 0.f, s2 = 0.f;
#pragma unroll
                for (int u = 0; u < 4; u++) {
                    x[v][u] = psum(acc[v][u]) + bpv[u];
                    s  += x[v][u];
                    s2 += x[v][u] * x[v][u];
                }
#pragma unroll
                for (int o = 16; o > 0; o >>= 1) {
                    s  += __shfl_xor_sync(0xffffffffu, s,  o);
                    s2 += __shfl_xor_sync(0xffffffffu, s2, o);
                }
                if (lane == 0) {
                    sRedA[(8 * wm + v) * 4 + 2 * wn + 0] = s;
                    sRedA[(8 * wm + v) * 4 + 2 * wn + 1] = s2;
                }
            }
            __syncthreads();
#pragma unroll
            for (int v = 0; v < 8; v++) {
                int row = 8 * wm + v;
                float s  = sRedA[row * 4 + 0] + sRedA[row * 4 + 2];
                float s2 = sRedA[row * 4 + 1] + sRedA[row * 4 + 3];
                float mean = s * (1.0f / 256.0f);
                float var  = s2 * (1.0f / 256.0f) - mean * mean;
                float inv  = rsqrtf(var + 1e-5f);
#pragma unroll
                for (int u = 0; u < 4; u++) x[v][u] = (x[v][u] - mean) * inv;
            }
            // pack LN(p) quads into sP4: [i4][n][2] u64
#pragma unroll
            for (int q4 = 0; q4 < 2; q4++) {
                int i4 = 2 * wm + q4;
#pragma unroll
                for (int u = 0; u < 4; u++) {
                    int n = 128 * wn + 32 * u + lane;
                    ulonglong2 t;
                    t.x = pk(x[4 * q4 + 0][u], x[4 * q4 + 1][u]);
                    t.y = pk(x[4 * q4 + 2][u], x[4 * q4 + 3][u]);
                    *(ulonglong2*)&sP4[i4 * 512 + n * 2] = t;
                }
            }
            __syncthreads();

            // r-partial einsum: lin_r[j][d] = sum_i A[i][j] * p[i][d]  (K = 64 i = 16 i4)
            u64 acc2[8][4];
#pragma unroll
            for (int v = 0; v < 8; v++)
#pragma unroll
                for (int u = 0; u < 4; u++) acc2[v][u] = 0ull;
#pragma unroll 2
            for (int i4 = 0; i4 < 16; i4++) {
                u64 w0[4], w1[4];
#pragma unroll
                for (int u = 0; u < 4; u++) {
                    ulonglong2 ww = *(const ulonglong2*)&sP4[i4 * 512 + (128 * wn + 32 * u + lane) * 2];
                    w0[u] = ww.x; w1[u] = ww.y;
                }
#pragma unroll
                for (int v = 0; v < 8; v++) {
                    ulonglong2 aa = As4[i4 * 64 + 8 * wm + v];
#pragma unroll
                    for (int u = 0; u < 4; u++) {
                        fma2(acc2[v][u], aa.x, w0[u]);
                        fma2(acc2[v][u], aa.y, w1[u]);
                    }
                }
            }
            // write 64KB partial
#pragma unroll
            for (int v = 0; v < 8; v++) {
                int j = 8 * wm + v;
#pragma unroll
                for (int u = 0; u < 4; u++) {
                    int n = 128 * wn + 32 * u + lane;
                    g_p[((grp * 8 + r) * 64 + j) * 256 + n] = psum(acc2[v][u]);
                }
            }
        }
        gsync_grp(grp);

        // ---------- phase B: partial sum + shrink + LN + gate + outGEMM + tanh + mask ----------
        {
            const int j0 = r * 8;
            const int wn4 = w & 3, ws = w >> 2;          // 4 col-groups x 4 k-slices
            u64*   bufu   = (u64*)sm;                    // [2][8192]
            float* sH     = sm + 32768;                  // [8][256]
            float* sRedLN = sm + 34816;                  // 64
            float* redK   = sm + 34880;                  // [4][2048]

            // ----- partial reduction + shrink + LN + gate (warp = (row v8, col-half ch)) -----
            const int v8 = w >> 1, ch = w & 1;
            const int gr = grp * 64 + j0 + v8;
            float tv4[4], s = 0.f, s2 = 0.f;
#pragma unroll
            for (int u = 0; u < 4; u++) {
                int n = ch * 128 + 32 * u + lane;
                float lin = 0.f;
#pragma unroll
                for (int r8 = 0; r8 < 8; r8++)
                    lin += __ldcg(&g_p[((grp * 8 + r8) * 64 + j0 + v8) * 256 + n]);
                float tv = __ldg(&g_ssp[2][gr * 256 + n]) + lin - tanhf(lin);
                tv4[u] = tv;
                s += tv; s2 += tv * tv;
            }
#pragma unroll
            for (int o = 16; o > 0; o >>= 1) {
                s  += __shfl_xor_sync(0xffffffffu, s,  o);
                s2 += __shfl_xor_sync(0xffffffffu, s2, o);
            }
            if (lane == 0) {
                sRedLN[v8 * 4 + 2 * ch + 0] = s;
                sRedLN[v8 * 4 + 2 * ch + 1] = s2;
            }
            __syncthreads();
            {
                float ts  = sRedLN[v8 * 4 + 0] + sRedLN[v8 * 4 + 2];
                float ts2 = sRedLN[v8 * 4 + 1] + sRedLN[v8 * 4 + 3];
                float mean = ts * (1.0f / 256.0f);
                float var  = ts2 * (1.0f / 256.0f) - mean * mean;
                float inv  = rsqrtf(var + 1e-5f);
#pragma unroll
                for (int u = 0; u < 4; u++) {
                    int n = ch * 128 + 32 * u + lane;
                    float ln = (tv4[u] - mean) * inv;
                    float hv = __ldg(&g_ssp[0][gr * 256 + n]) * ln + __ldg(&g_ssp[1][gr * 256 + n]);
                    sH[v8 * 256 + n] = fmaxf(hv, 0.0f);
                }
            }
            __syncthreads();

            // ----- out GEMM: y = tanh(h @ Wout + bout), K=256: 4 chunks of 32 k2 -----
            u64 acc2[8][2];
#pragma unroll
            for (int v = 0; v < 8; v++) { acc2[v][0] = 0ull; acc2[v][1] = 0ull; }
            const float4* wo = (const float4*)g_wo2;
            float4 wreg[8];
#pragma unroll
            for (int q = 0; q < 8; q++) wreg[q] = __ldg(&wo[q * NT + tid]);
            {
                float4* d0 = (float4*)bufu;
#pragma unroll
                for (int q = 0; q < 8; q++) d0[q * NT + tid] = wreg[q];
            }
            __syncthreads();
            for (int kc = 0; kc < 4; kc++) {
                if (kc < 3) {
#pragma unroll
                    for (int q = 0; q < 8; q++)
                        wreg[q] = __ldg(&wo[(kc + 1) * 4096 + q * NT + tid]);
                }
                gemmB(acc2, bufu + (kc & 1) * 8192, (const u64*)sH, 128, kc * 32, wn4, lane, ws);
                if (kc < 3) {
                    float4* dn = (float4*)(bufu + ((kc + 1) & 1) * 8192);
#pragma unroll
                    for (int q = 0; q < 8; q++) dn[q * NT + tid] = wreg[q];
                }
                __syncthreads();
            }
            // ----- epilogue: k-split reduce + tanh + mask -----
#pragma unroll
            for (int v = 0; v < 8; v++)
#pragma unroll
                for (int u = 0; u < 2; u++) {
                    int n = 64 * wn4 + 32 * u + lane;
                    redK[ws * 2048 + v * 256 + n] = psum(acc2[v][u]);
                }
            __syncthreads();
            {
                bool mz = ((64 - st) > g_len[grp]);
#pragma unroll
                for (int u = 0; u < 4; u++) {
                    int n = ch * 128 + 32 * u + lane;
                    float lin = redK[v8 * 256 + n] + redK[2048 + v8 * 256 + n]
                              + redK[4096 + v8 * 256 + n] + redK[6144 + v8 * 256 + n]
                              + __ldg(&bout[n]);
                    float yv = tanhf(lin);
                    g_h[gr * 256 + n] = mz ? 0.0f : yv;
                }
            }
        }
        gsync_grp(grp);
    }

    // =================== final reduction (group leader CTA) ===================
    if (r == 0 && tid < 256) {
        float sdot = 0.0f;
        for (int i = 0; i < 64; i++)
            sdot += __ldcg(&g_h[(grp * 64 + i) * 256 + tid]) * __ldg(&root[grp * 64 + i]);
        out[grp * 256 + tid] = sdot;
    }
}

extern "C" void kernel_launch(void* const* d_in, const int* in_sizes, int n_in,
                              void* d_out, int out_size) {
    const int*   tokens = (const int*)  d_in[0];
    const float* A      = (const float*)d_in[1];
    const float* root   = (const float*)d_in[2];
    const float* emb    = (const float*)d_in[3];
    const float* Wp     = (const float*)d_in[4];
    const float* bp     = (const float*)d_in[5];
    const float* W_in   = (const float*)d_in[6];
    const float* b_in   = (const float*)d_in[7];
    const float* Wout   = (const float*)d_in[8];
    const float* bout   = (const float*)d_in[9];
    float* out = (float*)d_out;

    cudaFuncSetAttribute(k_persist, cudaFuncAttributeMaxDynamicSharedMemorySize, SMEM_BYTES);
    k_persist<<<NB, NT, SMEM_BYTES>>>(tokens, A, root, emb, Wp, bp, W_in, b_in, Wout, bout, out);
}